// round 12
// baseline (speedup 1.0000x reference)
#include <cuda_runtime.h>
#include <cuda_bf16.h>
#include <math.h>
#include <stdint.h>

typedef unsigned long long ull;
typedef unsigned short u16;

__device__ __forceinline__ ull pk2(float lo, float hi) {
    ull r; asm("mov.b64 %0, {%1, %2};" : "=l"(r) : "f"(lo), "f"(hi)); return r;
}
__device__ __forceinline__ ull bc2(float v) {
    ull r; asm("mov.b64 %0, {%1, %1};" : "=l"(r) : "f"(v)); return r;
}
__device__ __forceinline__ void fma2(ull& d, ull a, ull b) {
    asm("fma.rn.f32x2 %0, %1, %2, %0;" : "+l"(d) : "l"(a), "l"(b));
}
__device__ __forceinline__ void up2(float& lo, float& hi, ull v) {
    asm("mov.b64 {%0, %1}, %2;" : "=f"(lo), "=f"(hi) : "l"(v));
}
__device__ __forceinline__ uint32_t smem_u32(const void* p) {
    uint32_t a;
    asm("{ .reg .u64 t; cvta.to.shared.u64 t, %1; cvt.u32.u64 %0, t; }" : "=r"(a) : "l"(p));
    return a;
}
#define CPA16(dst, src) asm volatile( \
    "cp.async.ca.shared.global [%0], [%1], 16;" :: "r"(dst), "l"(src))
#define CP_COMMIT() asm volatile("cp.async.commit_group;" ::: "memory")
#define CP_WAIT0() asm volatile("cp.async.wait_group 0;" ::: "memory")
#define LDSM4(R, a) asm volatile( \
    "ldmatrix.sync.aligned.m8n8.x4.shared.b16 {%0,%1,%2,%3},[%4];" \
    : "=r"((R)[0]), "=r"((R)[1]), "=r"((R)[2]), "=r"((R)[3]) : "r"(a))
#define LDSM2(R, a) asm volatile( \
    "ldmatrix.sync.aligned.m8n8.x2.shared.b16 {%0,%1},[%2];" \
    : "=r"((R)[0]), "=r"((R)[1]) : "r"(a))
#define MMA(D, A, B) asm volatile( \
    "mma.sync.aligned.m16n8k16.row.col.f32.bf16.bf16.f32 " \
    "{%0,%1,%2,%3},{%4,%5,%6,%7},{%8,%9},{%0,%1,%2,%3};" \
    : "+f"((D)[0]), "+f"((D)[1]), "+f"((D)[2]), "+f"((D)[3]) \
    : "r"((A)[0]), "r"((A)[1]), "r"((A)[2]), "r"((A)[3]), "r"((B)[0]), "r"((B)[1]))

// -------- scratch globals --------
__device__ float g_bufA[67200000];   // h3 fp32 NCHW
__device__ u16 g_pAh[70000000];      // ping NHWC bf16 hi (padded)
__device__ u16 g_pAl[70000000];
__device__ u16 g_pBh[70000000];      // pong
__device__ u16 g_pBl[70000000];
__device__ uint4 g_wscr[150000];     // [kc32][tap][hl][oc][32] bf16
__device__ float g_latf[32768];
__device__ float g_latc[8192];
__device__ float g_ent[2048];
__device__ float g_routed[32768];
__device__ float g_thr;

#define OFF_ROUTED 1572864
#define OFF_GRAIN  1605632
#define OFF_ENT    1607680
#define OUT_FULL   1609728

// -------- encoder --------
__global__ void encoder_kernel(const float* __restrict__ x,
                               const float* __restrict__ We0, const float* __restrict__ be0,
                               const float* __restrict__ We1, const float* __restrict__ be1)
{
    int idx = blockIdx.x * blockDim.x + threadIdx.x;
    if (idx < 32768) {
        int n = idx >> 12, c = (idx >> 10) & 3, oy = (idx >> 5) & 31, ox = idx & 31;
        float acc = be0[c];
        for (int ic = 0; ic < 3; ic++)
            for (int ky = 0; ky < 3; ky++) {
                int iy = oy * 8 - 1 + ky;
                if ((unsigned)iy >= 256u) continue;
                for (int kx = 0; kx < 3; kx++) {
                    int ix = ox * 8 - 1 + kx;
                    if ((unsigned)ix >= 256u) continue;
                    acc += x[((n * 3 + ic) * 256 + iy) * 256 + ix] *
                           We0[((c * 3 + ic) * 3 + ky) * 3 + kx];
                }
            }
        g_latf[idx] = acc;
    } else if (idx < 40960) {
        int i2 = idx - 32768;
        int n = i2 >> 10, c = (i2 >> 8) & 3, oy = (i2 >> 4) & 15, ox = i2 & 15;
        float acc = be1[c];
        for (int ic = 0; ic < 3; ic++)
            for (int ky = 0; ky < 3; ky++) {
                int iy = oy * 16 - 1 + ky;
                if ((unsigned)iy >= 256u) continue;
                for (int kx = 0; kx < 3; kx++) {
                    int ix = ox * 16 - 1 + kx;
                    if ((unsigned)ix >= 256u) continue;
                    acc += x[((n * 3 + ic) * 256 + iy) * 256 + ix] *
                           We1[((c * 3 + ic) * 3 + ky) * 3 + kx];
                }
            }
        g_latc[i2] = acc;
    }
}

// -------- entropy / median / route --------
__global__ void entropy_kernel(const float* __restrict__ x)
{
    __shared__ float g[256];
    __shared__ float red[256];
    int bid = blockIdx.x;
    int b = bid >> 8, hp = (bid >> 4) & 15, wp = bid & 15;
    int tid = threadIdx.x;
    int gy = hp * 16 + (tid >> 4), gx = wp * 16 + (tid & 15);
    const float* xb = x + (size_t)b * 3 * 65536;
    g[tid] = 0.299f * xb[gy * 256 + gx] + 0.587f * xb[65536 + gy * 256 + gx]
           + 0.114f * xb[131072 + gy * 256 + gx];
    __syncthreads();
    for (int k = 2; k <= 256; k <<= 1)
        for (int j = k >> 1; j > 0; j >>= 1) {
            int ixj = tid ^ j;
            if (ixj > tid) {
                float a = g[tid], c2 = g[ixj];
                bool up = (tid & k) == 0;
                if ((a > c2) == up) { g[tid] = c2; g[ixj] = a; }
            }
            __syncthreads();
        }
    float vb = tid * (1.0f / 255.0f);
    float loV = vb - 0.0945f, hiV = vb + 0.0945f;
    int lo = 0, hi = 256;
    while (lo < hi) { int m = (lo + hi) >> 1; if (g[m] < loV) lo = m + 1; else hi = m; }
    int s0 = lo;
    lo = s0; hi = 256;
    while (lo < hi) { int m = (lo + hi) >> 1; if (g[m] <= hiV) lo = m + 1; else hi = m; }
    int s1 = lo;
    float S = 0.0f;
    for (int i = s0; i < s1; i++) {
        float d = (g[i] - vb) * 100.0f;
        S += expf(-0.5f * d * d);
    }
    red[tid] = S;
    __syncthreads();
    for (int st = 128; st > 0; st >>= 1) { if (tid < st) red[tid] += red[tid + st]; __syncthreads(); }
    float T = red[0];
    __syncthreads();
    float p = fmaxf(S / T, 1e-10f);
    red[tid] = p * log2f(p);
    __syncthreads();
    for (int st = 128; st > 0; st >>= 1) { if (tid < st) red[tid] += red[tid + st]; __syncthreads(); }
    if (tid == 0) g_ent[bid] = -red[0];
}

__global__ void median_kernel()
{
    __shared__ float s[2048];
    int tid = threadIdx.x;
    s[tid] = g_ent[tid]; s[tid + 1024] = g_ent[tid + 1024];
    __syncthreads();
    for (int k = 2; k <= 2048; k <<= 1)
        for (int j = k >> 1; j > 0; j >>= 1) {
            for (int base = 0; base < 2048; base += 1024) {
                int i = base + tid, ixj = i ^ j;
                if (ixj > i) {
                    float a = s[i], c2 = s[ixj];
                    bool up = (i & k) == 0;
                    if ((a > c2) == up) { s[i] = c2; s[ixj] = a; }
                }
            }
            __syncthreads();
        }
    if (tid == 0) g_thr = 0.5f * (s[1023] + s[1024]);
}

__global__ void route_kernel(float* __restrict__ out, int write_aux)
{
    int i = blockIdx.x * blockDim.x + threadIdx.x;
    if (i >= 32768) return;
    float thr = g_thr;
    int n = i >> 12, c = (i >> 10) & 3, y = (i >> 5) & 31, xx = i & 31;
    int hp = y >> 1, wp = xx >> 1;
    float e = g_ent[n * 256 + hp * 16 + wp];
    float v = (e > thr) ? g_latf[i] : g_latc[((n * 4 + c) * 16 + hp) * 16 + wp];
    g_routed[i] = v;
    if (write_aux) {
        out[OFF_ROUTED + i] = v;
        if (i < 2048) {
            float ev = g_ent[i];
            out[OFF_GRAIN + i] = (ev > thr) ? 1.0f : 0.0f;
            out[OFF_ENT + i] = ev;
        }
    }
}

// -------- scalar conv Wi: 4->256 @32x32, no relu, OUT = padded NHWC bf16 hi/lo --------
__global__ __launch_bounds__(256, 2) void convWi_kernel(
    const float* __restrict__ in, const float* __restrict__ w,
    const float* __restrict__ bias, u16* __restrict__ oh, u16* __restrict__ ol)
{
    const int C_in = 4, H = 32, W = 32;
    __shared__ __align__(16) float s_in[4][18][20];
    __shared__ ull s_w2[4][9][64];
    int tiles_x = 2;
    int ty = blockIdx.x / tiles_x, tx = blockIdx.x - ty * tiles_x;
    int oc0 = blockIdx.y << 6, n = blockIdx.z;
    int y0 = ty << 4, x0 = tx << 4;
    int tid = threadIdx.x;
    int ocg = tid >> 4, pxg = tid & 15;
    int pr4 = (pxg >> 2) << 2, pc4 = (pxg & 3) << 2;
    ull acc[4][4][2];
    #pragma unroll
    for (int o = 0; o < 4; o++)
        #pragma unroll
        for (int r = 0; r < 4; r++) { acc[o][r][0] = 0; acc[o][r][1] = 0; }
    const float* in_n = in + (size_t)n * C_in * H * W;
    {
        __syncthreads();
        for (int e = tid; e < 4 * 324; e += 256) {
            int ic = e / 324, rem = e - ic * 324;
            int r = rem / 18, cc = rem - r * 18;
            int gy = y0 - 1 + r, gx = x0 - 1 + cc;
            float v = 0.0f;
            if ((unsigned)gy < (unsigned)H && (unsigned)gx < (unsigned)W)
                v = in_n[((size_t)ic * H + gy) * W + gx];
            s_in[ic][r][cc] = v;
        }
        for (int e = tid; e < 4 * 576; e += 256) {
            int ic = e / 576, rem = e - ic * 576;
            int k = rem >> 6, oc = rem & 63;
            s_w2[ic][k][oc] = bc2(w[((size_t)(oc0 + oc) * C_in + ic) * 9 + k]);
        }
        __syncthreads();
        #pragma unroll 1
        for (int ic = 0; ic < 4; ic++)
            #pragma unroll
            for (int ky = 0; ky < 3; ky++) {
                ull w2[3][4];
                #pragma unroll
                for (int kx = 0; kx < 3; kx++)
                    #pragma unroll
                    for (int o = 0; o < 4; o++) w2[kx][o] = s_w2[ic][ky * 3 + kx][(ocg << 2) + o];
                #pragma unroll
                for (int r = 0; r < 4; r++) {
                    const float* rp = &s_in[ic][pr4 + r + ky][pc4];
                    float4 v4 = *(const float4*)rp;
                    float2 v2 = *(const float2*)(rp + 4);
                    ull P0 = pk2(v4.x, v4.y), P1 = pk2(v4.y, v4.z), P2 = pk2(v4.z, v4.w);
                    ull P3 = pk2(v4.w, v2.x), P4 = pk2(v2.x, v2.y);
                    #pragma unroll
                    for (int o = 0; o < 4; o++) {
                        fma2(acc[o][r][0], w2[0][o], P0);
                        fma2(acc[o][r][1], w2[0][o], P2);
                        fma2(acc[o][r][0], w2[1][o], P1);
                        fma2(acc[o][r][1], w2[1][o], P3);
                        fma2(acc[o][r][0], w2[2][o], P2);
                        fma2(acc[o][r][1], w2[2][o], P4);
                    }
                }
            }
    }
    float bv[4];
    #pragma unroll
    for (int o = 0; o < 4; o++) bv[o] = bias[oc0 + (ocg << 2) + o];
    #pragma unroll
    for (int r = 0; r < 4; r++) {
        float vv[4][4];
        #pragma unroll
        for (int o = 0; o < 4; o++) {
            up2(vv[o][0], vv[o][1], acc[o][r][0]);
            up2(vv[o][2], vv[o][3], acc[o][r][1]);
            #pragma unroll
            for (int c = 0; c < 4; c++) vv[o][c] += bv[o];
        }
        int gy = y0 + pr4 + r + 1;
        #pragma unroll
        for (int c = 0; c < 4; c++) {
            u16 hv[4], lv[4];
            #pragma unroll
            for (int o = 0; o < 4; o++) {
                __nv_bfloat16 h = __float2bfloat16(vv[o][c]);
                hv[o] = __bfloat16_as_ushort(h);
                lv[o] = __bfloat16_as_ushort(__float2bfloat16(vv[o][c] - __bfloat162float(h)));
            }
            size_t off = ((size_t)(n * 34 + gy) * 34 + x0 + pc4 + c + 1) * 256 + oc0 + (ocg << 2);
            *(uint2*)&oh[off] = *(uint2*)hv;
            *(uint2*)&ol[off] = *(uint2*)lv;
        }
    }
}

// -------- Wo conv: 128->3, tanh (reads fp32 NCHW) --------
__global__ __launch_bounds__(256) void convWo_kernel(
    const float* __restrict__ in, const float* __restrict__ w,
    const float* __restrict__ bias, float* __restrict__ out)
{
    __shared__ float s_w[3456];
    __shared__ __align__(16) float s_in[2][10][260];
    int n = blockIdx.x >> 5;
    int y0 = (blockIdx.x & 31) << 3;
    int tid = threadIdx.x;
    int rowg = tid >> 6;
    int c4 = (tid & 63) << 2;
    for (int e = tid; e < 3456; e += 256) s_w[e] = w[e];
    ull acc[3][2][2];
    #pragma unroll
    for (int ch = 0; ch < 3; ch++)
        #pragma unroll
        for (int r = 0; r < 2; r++) { acc[ch][r][0] = 0; acc[ch][r][1] = 0; }
    const float* in_n = in + (size_t)n * 128 * 65536;
    for (int ic0 = 0; ic0 < 128; ic0 += 2) {
        __syncthreads();
        for (int e = tid; e < 2 * 2580; e += 256) {
            int ic = e / 2580, rem = e - ic * 2580;
            int rr = rem / 258, cc = rem - rr * 258;
            int gy = y0 - 1 + rr, gx = cc - 1;
            float v = 0.0f;
            if ((unsigned)gy < 256u && (unsigned)gx < 256u)
                v = in_n[(size_t)(ic0 + ic) * 65536 + gy * 256 + gx];
            s_in[ic][rr][cc] = v;
        }
        __syncthreads();
        #pragma unroll
        for (int ic = 0; ic < 2; ic++)
            #pragma unroll
            for (int ky = 0; ky < 3; ky++) {
                ull P[2][5];
                #pragma unroll
                for (int r = 0; r < 2; r++) {
                    const float* rp = &s_in[ic][(rowg << 1) + r + ky][c4];
                    float4 v4 = *(const float4*)rp;
                    float2 v2 = *(const float2*)(rp + 4);
                    P[r][0] = pk2(v4.x, v4.y); P[r][1] = pk2(v4.y, v4.z);
                    P[r][2] = pk2(v4.z, v4.w); P[r][3] = pk2(v4.w, v2.x);
                    P[r][4] = pk2(v2.x, v2.y);
                }
                #pragma unroll
                for (int kx = 0; kx < 3; kx++)
                    #pragma unroll
                    for (int ch = 0; ch < 3; ch++) {
                        ull wb = bc2(s_w[ch * 1152 + (ic0 + ic) * 9 + ky * 3 + kx]);
                        #pragma unroll
                        for (int r = 0; r < 2; r++) {
                            fma2(acc[ch][r][0], wb, P[r][kx]);
                            fma2(acc[ch][r][1], wb, P[r][kx + 2]);
                        }
                    }
            }
    }
    #pragma unroll
    for (int ch = 0; ch < 3; ch++) {
        float bv = bias[ch];
        #pragma unroll
        for (int r = 0; r < 2; r++) {
            int y = y0 + (rowg << 1) + r;
            float f0, f1, f2, f3;
            up2(f0, f1, acc[ch][r][0]); up2(f2, f3, acc[ch][r][1]);
            *(float4*)&out[((size_t)(n * 3 + ch) << 16) + y * 256 + c4] =
                make_float4(tanhf(f0 + bv), tanhf(f1 + bv), tanhf(f2 + bv), tanhf(f3 + bv));
        }
    }
}

// -------- MMA weight prep --------
__global__ void wprep_kernel(const float* __restrict__ w, int OC, int IC, int trans)
{
    int KC = IC >> 5;
    int tot = KC * 9 * OC * 32;
    u16* dst = (u16*)g_wscr;
    for (int idx = blockIdx.x * blockDim.x + threadIdx.x; idx < tot; idx += gridDim.x * blockDim.x) {
        int j = idx & 31;
        int t = idx >> 5;
        int oc = t % OC; t /= OC;
        int tap = t % 9;
        int kc = t / 9;
        float v = trans ? w[((size_t)(kc * 32 + j) * OC + oc) * 9 + tap]
                        : w[((size_t)oc * IC + kc * 32 + j) * 9 + tap];
        __nv_bfloat16 h = __float2bfloat16(v);
        __nv_bfloat16 l = __float2bfloat16(v - __bfloat162float(h));
        size_t b = ((((size_t)kc * 9 + tap) * 2 + 0) * OC + oc) * 32 + j;
        size_t b2 = ((((size_t)kc * 9 + tap) * 2 + 1) * OC + oc) * 32 + j;
        dst[b] = __bfloat16_as_ushort(h);
        dst[b2] = __bfloat16_as_ushort(l);
    }
}

// -------- pad-ring zero --------
__global__ void ring_kernel(u16* __restrict__ oh, u16* __restrict__ ol, int C, int H, int W)
{
    int Hp = H + 2, Wp = W + 2, IC8 = C >> 3;
    int per = (2 * Wp + 2 * H) * IC8;
    int tot = 8 * per;
    uint4 z = make_uint4(0, 0, 0, 0);
    uint4* h4 = (uint4*)oh;
    uint4* l4 = (uint4*)ol;
    for (int idx = blockIdx.x * blockDim.x + threadIdx.x; idx < tot; idx += gridDim.x * blockDim.x) {
        int n = idx / per, r = idx % per;
        int pix = r / IC8, c = r % IC8;
        int y, x;
        if (pix < Wp) { y = 0; x = pix; }
        else if (pix < 2 * Wp) { y = Hp - 1; x = pix - Wp; }
        else { int q = pix - 2 * Wp; y = 1 + (q >> 1); x = (q & 1) ? Wp - 1 : 0; }
        size_t o = ((size_t)(n * Hp + y) * Wp + x) * IC8 + c;
        h4[o] = z; l4[o] = z;
    }
}

// -------- mma.sync conv 3x3 s1 p1 (3-pass hi/lo), cp.async, R rows/block --------
// Epilogue (mode 0): smem-transpose -> coalesced uint4 NHWC stores.
template<int NT, int R>
__global__ __launch_bounds__(256) void conv_mma_kernel(
    const u16* __restrict__ xh, const u16* __restrict__ xl,
    const float* __restrict__ bias,
    float* __restrict__ outf, u16* __restrict__ oh, u16* __restrict__ ol,
    int KC, int H, int W, int OC, int IC, int mode)
{
    extern __shared__ __align__(16) u16 sm[];
    const int PX = NT * 16;
    int segs = W / PX;
    int yb = blockIdx.x / segs, x0 = (blockIdx.x % segs) * PX;
    int y0 = yb * R;
    int oc0 = blockIdx.y << 7, n = blockIdx.z;
    int tid = threadIdx.x, wid = tid >> 5, l = tid & 31;
    int ocg = wid & 3, pxg = wid >> 2;
    int Hp = H + 2, Wp = W + 2;
    uint32_t sbase = smem_u32(sm);
    const u16* gw = (const u16*)g_wscr;
    float d[2][R][NT][4];
    #pragma unroll
    for (int mt = 0; mt < 2; mt++)
        #pragma unroll
        for (int r = 0; r < R; r++)
            #pragma unroll
            for (int nt = 0; nt < NT; nt++)
                #pragma unroll
                for (int i = 0; i < 4; i++) d[mt][r][nt][i] = 0.0f;

    const int pc = (PX + 2) * 4;
    for (int kc = 0; kc < KC; kc++)
        for (int ky = 0; ky < 3; ky++) {
            __syncthreads();
            for (int e = tid; e < 3072; e += 256) {
                int j8 = e & 3, oc = (e >> 2) & 127, blk = e >> 9;
                int kx = blk % 3, hl = blk / 3;
                const uint4* src = (const uint4*)(gw +
                    ((((size_t)kc * 9 + ky * 3 + kx) * 2 + hl) * OC + oc0 + oc) * 32) + j8;
                CPA16(sbase + (uint32_t)(blk * 128 + oc) * 80 + j8 * 16, src);
            }
            for (int e = tid; e < R * 2 * pc; e += 256) {
                int r = e / (2 * pc);
                int e2 = e - r * 2 * pc;
                int hl = e2 >= pc; int rr = e2 - hl * pc;
                int p = rr >> 2, j8 = rr & 3;
                const u16* gx = hl ? xl : xh;
                const uint4* src = (const uint4*)(gx +
                    ((size_t)(n * Hp + y0 + r + ky) * Wp + x0 + p) * IC + (kc << 5)) + j8;
                CPA16(sbase + 61440u + (uint32_t)((r * 2 + hl) * (PX + 2) + p) * 80 + j8 * 16, src);
            }
            CP_COMMIT();
            CP_WAIT0();
            __syncthreads();
            for (int kx = 0; kx < 3; kx++)
                #pragma unroll
                for (int ks = 0; ks < 2; ks++) {
                    uint32_t Ah[2][4], Al[2][4];
                    #pragma unroll
                    for (int mt = 0; mt < 2; mt++) {
                        int row = ocg * 32 + mt * 16 + (l & 15);
                        uint32_t a = sbase + (uint32_t)(kx * 128 + row) * 80 + ks * 32 + (l >> 4) * 16;
                        LDSM4(Ah[mt], a);
                        LDSM4(Al[mt], a + 3 * 128 * 80);
                    }
                    #pragma unroll
                    for (int r = 0; r < R; r++) {
                        uint32_t Bh[NT][2], Bl[NT][2];
                        #pragma unroll
                        for (int nt = 0; nt < NT; nt++) {
                            int p = pxg * (NT * 8) + nt * 8 + (l & 7) + kx;
                            uint32_t b = sbase + 61440 + (uint32_t)((r * 2) * (PX + 2) + p) * 80
                                       + ks * 32 + (((l & 15) >> 3) * 16);
                            LDSM2(Bh[nt], b);
                            LDSM2(Bl[nt], b + (PX + 2) * 80);
                        }
                        #pragma unroll
                        for (int mt = 0; mt < 2; mt++)
                            #pragma unroll
                            for (int nt = 0; nt < NT; nt++) {
                                MMA(d[mt][r][nt], Ah[mt], Bh[nt]);
                                MMA(d[mt][r][nt], Ah[mt], Bl[nt]);
                                MMA(d[mt][r][nt], Al[mt], Bh[nt]);
                            }
                    }
                }
        }
    if (mode) {
        size_t plane = (size_t)H * W;
        #pragma unroll
        for (int mt = 0; mt < 2; mt++) {
            int ocr = oc0 + ocg * 32 + mt * 16 + (l >> 2);
            float b0 = bias[ocr], b8 = bias[ocr + 8];
            #pragma unroll
            for (int r = 0; r < R; r++) {
                float* ob = outf + ((size_t)n * OC + ocr) * plane + (size_t)(y0 + r) * W;
                #pragma unroll
                for (int nt = 0; nt < NT; nt++) {
                    int px = x0 + pxg * (NT * 8) + nt * 8 + (l & 3) * 2;
                    *(float2*)(ob + px) = make_float2(
                        fmaxf(d[mt][r][nt][0] + b0, 0.0f), fmaxf(d[mt][r][nt][1] + b0, 0.0f));
                    *(float2*)(ob + 8 * plane + px) = make_float2(
                        fmaxf(d[mt][r][nt][2] + b8, 0.0f), fmaxf(d[mt][r][nt][3] + b8, 0.0f));
                }
            }
        }
    } else {
        const int PITCH = 136;
        u16* smh = sm;
        u16* sml = sm + PX * PITCH;
        for (int r = 0; r < R; r++) {
            __syncthreads();
            #pragma unroll
            for (int mt = 0; mt < 2; mt++) {
                int ocl = ocg * 32 + mt * 16 + (l >> 2);
                float b0 = bias[oc0 + ocl], b8 = bias[oc0 + ocl + 8];
                #pragma unroll
                for (int nt = 0; nt < NT; nt++) {
                    int pxl = pxg * (NT * 8) + nt * 8 + (l & 3) * 2;
                    #pragma unroll
                    for (int i = 0; i < 4; i++) {
                        int oc2 = ocl + ((i >> 1) << 3);
                        int px2 = pxl + (i & 1);
                        float v = fmaxf(d[mt][r][nt][i] + ((i >> 1) ? b8 : b0), 0.0f);
                        __nv_bfloat16 h = __float2bfloat16(v);
                        smh[px2 * PITCH + oc2] = __bfloat16_as_ushort(h);
                        sml[px2 * PITCH + oc2] =
                            __bfloat16_as_ushort(__float2bfloat16(v - __bfloat162float(h)));
                    }
                }
            }
            __syncthreads();
            for (int e = tid; e < PX * 16; e += 256) {
                int px = e >> 4, j8 = e & 15;
                size_t dst = ((size_t)(n * Hp + y0 + r + 1) * Wp + x0 + px + 1) * OC + oc0 + j8 * 8;
                *(uint4*)&oh[dst] = *(const uint4*)&smh[px * PITCH + j8 * 8];
                *(uint4*)&ol[dst] = *(const uint4*)&sml[px * PITCH + j8 * 8];
            }
        }
    }
}

// -------- mma.sync DECONV k3 s2 p1 op1 + relu, cp.async, coalesced epilogue --------
template<int NT>
__global__ __launch_bounds__(256) void deconv_mma_kernel(
    const u16* __restrict__ xh, const u16* __restrict__ xl,
    u16* __restrict__ oh, u16* __restrict__ ol,
    const float* __restrict__ bias,
    int KC, int H, int W, int OC, int IC)
{
    extern __shared__ __align__(16) u16 sm[];
    const int PX = NT * 16;
    int segs = W / PX;
    int y = blockIdx.x / segs, x0 = (blockIdx.x % segs) * PX;
    int oc0 = blockIdx.y << 7, n = blockIdx.z;
    int tid = threadIdx.x, wid = tid >> 5, l = tid & 31;
    int ocg = wid & 3, pxg = wid >> 2;
    int Hp = H + 2, Wp = W + 2;
    uint32_t sbase = smem_u32(sm);
    const u16* gw = (const u16*)g_wscr;
    float d[2][2][2][NT][4];                 // [mt][dy][dx][nt][4]
    #pragma unroll
    for (int mt = 0; mt < 2; mt++)
        #pragma unroll
        for (int a = 0; a < 2; a++)
            #pragma unroll
            for (int b = 0; b < 2; b++)
                #pragma unroll
                for (int nt = 0; nt < NT; nt++)
                    #pragma unroll
                    for (int i = 0; i < 4; i++) d[mt][a][b][nt][i] = 0.0f;

    const int pcd = (PX + 1) * 4;
    for (int kc = 0; kc < KC; kc++)
        for (int ky = 0; ky < 3; ky++) {
            __syncthreads();
            for (int e = tid; e < 3072; e += 256) {
                int j8 = e & 3, oc = (e >> 2) & 127, blk = e >> 9;
                int kx = blk % 3, hl = blk / 3;
                const uint4* src = (const uint4*)(gw +
                    ((((size_t)kc * 9 + ky * 3 + kx) * 2 + hl) * OC + oc0 + oc) * 32) + j8;
                CPA16(sbase + (uint32_t)(blk * 128 + oc) * 80 + j8 * 16, src);
            }
            int ry = y + 1 + (ky == 0);      // padded input row
            for (int e = tid; e < 2 * pcd; e += 256) {
                int hl = e >= pcd; int r = e - hl * pcd;
                int p = r >> 2, j8 = r & 3;
                const u16* gx = hl ? xl : xh;
                const uint4* src = (const uint4*)(gx +
                    ((size_t)(n * Hp + ry) * Wp + x0 + 1 + p) * IC + (kc << 5)) + j8;
                CPA16(sbase + 61440u + (uint32_t)(hl * (PX + 1) + p) * 80 + j8 * 16, src);
            }
            CP_COMMIT();
            CP_WAIT0();
            __syncthreads();
            int dy = (ky != 1);
            #pragma unroll
            for (int ks = 0; ks < 2; ks++) {
                uint32_t Bf[2][2][NT][2];    // [hl][shift][nt][2]
                #pragma unroll
                for (int sh = 0; sh < 2; sh++)
                    #pragma unroll
                    for (int nt = 0; nt < NT; nt++) {
                        int p = pxg * (NT * 8) + nt * 8 + (l & 7) + sh;
                        uint32_t b = sbase + 61440 + (uint32_t)p * 80 + ks * 32 + (((l & 15) >> 3) * 16);
                        LDSM2(Bf[0][sh][nt], b);
                        LDSM2(Bf[1][sh][nt], b + (PX + 1) * 80);
                    }
                for (int kx = 0; kx < 3; kx++) {
                    int sh = (kx == 0), dxp = (kx != 1);
                    uint32_t Ah[2][4], Al[2][4];
                    #pragma unroll
                    for (int mt = 0; mt < 2; mt++) {
                        int row = ocg * 32 + mt * 16 + (l & 15);
                        uint32_t a = sbase + (uint32_t)(kx * 128 + row) * 80 + ks * 32 + (l >> 4) * 16;
                        LDSM4(Ah[mt], a);
                        LDSM4(Al[mt], a + 3 * 128 * 80);
                    }
                    #pragma unroll
                    for (int mt = 0; mt < 2; mt++)
                        #pragma unroll
                        for (int nt = 0; nt < NT; nt++) {
                            MMA(d[mt][dy][dxp][nt], Ah[mt], Bf[0][sh][nt]);
                            MMA(d[mt][dy][dxp][nt], Ah[mt], Bf[1][sh][nt]);
                            MMA(d[mt][dy][dxp][nt], Al[mt], Bf[0][sh][nt]);
                        }
                }
            }
        }
    int OHp = 2 * H + 2, OWp = 2 * W + 2;
    const int PITCH = 136;
    u16* smh = sm;
    u16* sml = sm + (2 * PX) * PITCH;
    for (int dy2 = 0; dy2 < 2; dy2++) {
        __syncthreads();
        #pragma unroll
        for (int mt = 0; mt < 2; mt++) {
            int ocl = ocg * 32 + mt * 16 + (l >> 2);
            float b0 = bias[oc0 + ocl], b8 = bias[oc0 + ocl + 8];
            #pragma unroll
            for (int dxp = 0; dxp < 2; dxp++)
                #pragma unroll
                for (int nt = 0; nt < NT; nt++) {
                    int p0l = pxg * (NT * 8) + nt * 8 + 2 * (l & 3);
                    #pragma unroll
                    for (int i = 0; i < 4; i++) {
                        int oc2 = ocl + ((i >> 1) << 3);
                        int c = 2 * (p0l + (i & 1)) + dxp;
                        float v = fmaxf(d[mt][dy2][dxp][nt][i] + ((i >> 1) ? b8 : b0), 0.0f);
                        __nv_bfloat16 h = __float2bfloat16(v);
                        smh[c * PITCH + oc2] = __bfloat16_as_ushort(h);
                        sml[c * PITCH + oc2] =
                            __bfloat16_as_ushort(__float2bfloat16(v - __bfloat162float(h)));
                    }
                }
        }
        __syncthreads();
        for (int e = tid; e < 2 * PX * 16; e += 256) {
            int px = e >> 4, j8 = e & 15;
            size_t dst = ((size_t)(n * OHp + 2 * y + dy2 + 1) * OWp + 2 * x0 + 1 + px) * OC
                       + oc0 + j8 * 8;
            *(uint4*)&oh[dst] = *(const uint4*)&smh[px * PITCH + j8 * 8];
            *(uint4*)&ol[dst] = *(const uint4*)&sml[px * PITCH + j8 * 8];
        }
    }
}

// -------- host --------
static void conv_mma(const float* w, const float* b, const u16* xh, const u16* xl,
                     u16* oh, u16* ol, float* outf, int IC, int OC, int H, int W, int mode)
{
    wprep_kernel<<<128, 256>>>(w, OC, IC, 0);
    if (mode == 0) ring_kernel<<<256, 256>>>(oh, ol, OC, H, W);
    if (W >= 128) {
        dim3 grid((W / 128) * (H / 2), OC / 128, 8);
        conv_mma_kernel<8, 2><<<grid, 256, 61440 + 2 * 2 * 130 * 80>>>(
            xh, xl, b, outf, oh, ol, IC / 32, H, W, OC, IC, mode);
    } else {
        dim3 grid((W / 64) * (H / 2), OC / 128, 8);
        conv_mma_kernel<4, 2><<<grid, 256, 61440 + 2 * 2 * 66 * 80>>>(
            xh, xl, b, outf, oh, ol, IC / 32, H, W, OC, IC, mode);
    }
}

static void deconv_mma(const float* w, const float* b, const u16* xh, const u16* xl,
                       u16* oh, u16* ol, int IC, int OC, int H, int W)
{
    wprep_kernel<<<128, 256>>>(w, OC, IC, 1);
    ring_kernel<<<256, 256>>>(oh, ol, OC, 2 * H, 2 * W);
    if (W >= 64) {
        dim3 grid((W / 64) * H, OC / 128, 8);
        deconv_mma_kernel<4><<<grid, 256, 71840>>>(xh, xl, oh, ol, b, IC / 32, H, W, OC, IC);
    } else {
        dim3 grid((W / 32) * H, OC / 128, 8);
        deconv_mma_kernel<2><<<grid, 256, 66880>>>(xh, xl, oh, ol, b, IC / 32, H, W, OC, IC);
    }
}

extern "C" void kernel_launch(void* const* d_in, const int* in_sizes, int n_in,
                              void* d_out, int out_size)
{
    const float* x   = (const float*)d_in[0];
    const float* We0 = (const float*)d_in[1];
    const float* be0 = (const float*)d_in[2];
    const float* We1 = (const float*)d_in[3];
    const float* be1 = (const float*)d_in[4];
    const float* Wi  = (const float*)d_in[5];
    const float* bi  = (const float*)d_in[6];
    const float* Wd1 = (const float*)d_in[7];
    const float* bd1 = (const float*)d_in[8];
    const float* Wc1 = (const float*)d_in[9];
    const float* bc1 = (const float*)d_in[10];
    const float* Wd2 = (const float*)d_in[11];
    const float* bd2 = (const float*)d_in[12];
    const float* Wc2 = (const float*)d_in[13];
    const float* bc2_ = (const float*)d_in[14];
    const float* Wd3 = (const float*)d_in[15];
    const float* bd3 = (const float*)d_in[16];
    const float* Wc3 = (const float*)d_in[17];
    const float* bc3 = (const float*)d_in[18];
    const float* Wo  = (const float*)d_in[19];
    const float* bo  = (const float*)d_in[20];
    float* out = (float*)d_out;

    static int once = 0;
    if (!once) {
        cudaFuncSetAttribute(conv_mma_kernel<8, 2>, cudaFuncAttributeMaxDynamicSharedMemorySize, 104000);
        cudaFuncSetAttribute(conv_mma_kernel<4, 2>, cudaFuncAttributeMaxDynamicSharedMemorySize, 104000);
        cudaFuncSetAttribute(deconv_mma_kernel<4>, cudaFuncAttributeMaxDynamicSharedMemorySize, 104000);
        cudaFuncSetAttribute(deconv_mma_kernel<2>, cudaFuncAttributeMaxDynamicSharedMemorySize, 104000);
        once = 1;
    }

    float *h3buf, *routed;
    u16 *pAh, *pAl, *pBh, *pBl;
    cudaGetSymbolAddress((void**)&h3buf, g_bufA);
    cudaGetSymbolAddress((void**)&routed, g_routed);
    cudaGetSymbolAddress((void**)&pAh, g_pAh);
    cudaGetSymbolAddress((void**)&pAl, g_pAl);
    cudaGetSymbolAddress((void**)&pBh, g_pBh);
    cudaGetSymbolAddress((void**)&pBl, g_pBl);

    encoder_kernel<<<160, 256>>>(x, We0, be0, We1, be1);
    entropy_kernel<<<2048, 256>>>(x);
    median_kernel<<<1, 1024>>>();
    int write_aux = (out_size >= OUT_FULL) ? 1 : 0;
    route_kernel<<<128, 256>>>(out, write_aux);

    ring_kernel<<<256, 256>>>(pAh, pAl, 256, 32, 32);
    dim3 gWi(4, 4, 8);
    convWi_kernel<<<gWi, 256>>>(routed, Wi, bi, pAh, pAl);
    deconv_mma(Wd1, bd1, pAh, pAl, pBh, pBl, 256, 256, 32, 32);
    conv_mma(Wc1, bc1, pBh, pBl, pAh, pAl, nullptr, 256, 256, 64, 64, 0);
    deconv_mma(Wd2, bd2, pAh, pAl, pBh, pBl, 256, 128, 64, 64);
    conv_mma(Wc2, bc2_, pBh, pBl, pAh, pAl, nullptr, 128, 128, 128, 128, 0);
    deconv_mma(Wd3, bd3, pAh, pAl, pBh, pBl, 128, 128, 128, 128);
    conv_mma(Wc3, bc3, pBh, pBl, nullptr, nullptr, h3buf, 128, 128, 256, 256, 1);
    convWo_kernel<<<256, 256>>>(h3buf, Wo, bo, out);
}

// round 13
// speedup vs baseline: 1.8378x; 1.8378x over previous
#include <cuda_runtime.h>
#include <cuda_bf16.h>
#include <math.h>
#include <stdint.h>

typedef unsigned long long ull;
typedef unsigned short u16;

__device__ __forceinline__ ull pk2(float lo, float hi) {
    ull r; asm("mov.b64 %0, {%1, %2};" : "=l"(r) : "f"(lo), "f"(hi)); return r;
}
__device__ __forceinline__ ull bc2(float v) {
    ull r; asm("mov.b64 %0, {%1, %1};" : "=l"(r) : "f"(v)); return r;
}
__device__ __forceinline__ void fma2(ull& d, ull a, ull b) {
    asm("fma.rn.f32x2 %0, %1, %2, %0;" : "+l"(d) : "l"(a), "l"(b));
}
__device__ __forceinline__ void up2(float& lo, float& hi, ull v) {
    asm("mov.b64 {%0, %1}, %2;" : "=f"(lo), "=f"(hi) : "l"(v));
}
__device__ __forceinline__ uint32_t smem_u32(const void* p) {
    uint32_t a;
    asm("{ .reg .u64 t; cvta.to.shared.u64 t, %1; cvt.u32.u64 %0, t; }" : "=r"(a) : "l"(p));
    return a;
}
__device__ __forceinline__ void stsplit(u16* __restrict__ oh, u16* __restrict__ ol,
                                        size_t o, float v)
{
    __nv_bfloat16 h = __float2bfloat16(v);
    oh[o] = __bfloat16_as_ushort(h);
    ol[o] = __bfloat16_as_ushort(__float2bfloat16(v - __bfloat162float(h)));
}
#define CPA16(dst, src) asm volatile( \
    "cp.async.ca.shared.global [%0], [%1], 16;" :: "r"(dst), "l"(src))
#define CP_COMMIT() asm volatile("cp.async.commit_group;" ::: "memory")
#define CP_WAIT0() asm volatile("cp.async.wait_group 0;" ::: "memory")
#define LDSM4(R, a) asm volatile( \
    "ldmatrix.sync.aligned.m8n8.x4.shared.b16 {%0,%1,%2,%3},[%4];" \
    : "=r"((R)[0]), "=r"((R)[1]), "=r"((R)[2]), "=r"((R)[3]) : "r"(a))
#define LDSM2(R, a) asm volatile( \
    "ldmatrix.sync.aligned.m8n8.x2.shared.b16 {%0,%1},[%2];" \
    : "=r"((R)[0]), "=r"((R)[1]) : "r"(a))
#define MMA(D, A, B) asm volatile( \
    "mma.sync.aligned.m16n8k16.row.col.f32.bf16.bf16.f32 " \
    "{%0,%1,%2,%3},{%4,%5,%6,%7},{%8,%9},{%0,%1,%2,%3};" \
    : "+f"((D)[0]), "+f"((D)[1]), "+f"((D)[2]), "+f"((D)[3]) \
    : "r"((A)[0]), "r"((A)[1]), "r"((A)[2]), "r"((A)[3]), "r"((B)[0]), "r"((B)[1]))

// -------- scratch globals --------
__device__ float g_bufA[67200000];   // h3 fp32 NCHW
__device__ u16 g_pAh[70000000];      // ping NHWC bf16 hi (padded)
__device__ u16 g_pAl[70000000];
__device__ u16 g_pBh[70000000];      // pong
__device__ u16 g_pBl[70000000];
__device__ uint4 g_wscr[150000];     // [kc32][tap][hl][oc][32] bf16
__device__ float g_latf[32768];
__device__ float g_latc[8192];
__device__ float g_ent[2048];
__device__ float g_routed[32768];
__device__ float g_thr;

#define OFF_ROUTED 1572864
#define OFF_GRAIN  1605632
#define OFF_ENT    1607680
#define OUT_FULL   1609728

// -------- encoder --------
__global__ void encoder_kernel(const float* __restrict__ x,
                               const float* __restrict__ We0, const float* __restrict__ be0,
                               const float* __restrict__ We1, const float* __restrict__ be1)
{
    int idx = blockIdx.x * blockDim.x + threadIdx.x;
    if (idx < 32768) {
        int n = idx >> 12, c = (idx >> 10) & 3, oy = (idx >> 5) & 31, ox = idx & 31;
        float acc = be0[c];
        for (int ic = 0; ic < 3; ic++)
            for (int ky = 0; ky < 3; ky++) {
                int iy = oy * 8 - 1 + ky;
                if ((unsigned)iy >= 256u) continue;
                for (int kx = 0; kx < 3; kx++) {
                    int ix = ox * 8 - 1 + kx;
                    if ((unsigned)ix >= 256u) continue;
                    acc += x[((n * 3 + ic) * 256 + iy) * 256 + ix] *
                           We0[((c * 3 + ic) * 3 + ky) * 3 + kx];
                }
            }
        g_latf[idx] = acc;
    } else if (idx < 40960) {
        int i2 = idx - 32768;
        int n = i2 >> 10, c = (i2 >> 8) & 3, oy = (i2 >> 4) & 15, ox = i2 & 15;
        float acc = be1[c];
        for (int ic = 0; ic < 3; ic++)
            for (int ky = 0; ky < 3; ky++) {
                int iy = oy * 16 - 1 + ky;
                if ((unsigned)iy >= 256u) continue;
                for (int kx = 0; kx < 3; kx++) {
                    int ix = ox * 16 - 1 + kx;
                    if ((unsigned)ix >= 256u) continue;
                    acc += x[((n * 3 + ic) * 256 + iy) * 256 + ix] *
                           We1[((c * 3 + ic) * 3 + ky) * 3 + kx];
                }
            }
        g_latc[i2] = acc;
    }
}

// -------- entropy / median / route --------
__global__ void entropy_kernel(const float* __restrict__ x)
{
    __shared__ float g[256];
    __shared__ float red[256];
    int bid = blockIdx.x;
    int b = bid >> 8, hp = (bid >> 4) & 15, wp = bid & 15;
    int tid = threadIdx.x;
    int gy = hp * 16 + (tid >> 4), gx = wp * 16 + (tid & 15);
    const float* xb = x + (size_t)b * 3 * 65536;
    g[tid] = 0.299f * xb[gy * 256 + gx] + 0.587f * xb[65536 + gy * 256 + gx]
           + 0.114f * xb[131072 + gy * 256 + gx];
    __syncthreads();
    for (int k = 2; k <= 256; k <<= 1)
        for (int j = k >> 1; j > 0; j >>= 1) {
            int ixj = tid ^ j;
            if (ixj > tid) {
                float a = g[tid], c2 = g[ixj];
                bool up = (tid & k) == 0;
                if ((a > c2) == up) { g[tid] = c2; g[ixj] = a; }
            }
            __syncthreads();
        }
    float vb = tid * (1.0f / 255.0f);
    float loV = vb - 0.0945f, hiV = vb + 0.0945f;
    int lo = 0, hi = 256;
    while (lo < hi) { int m = (lo + hi) >> 1; if (g[m] < loV) lo = m + 1; else hi = m; }
    int s0 = lo;
    lo = s0; hi = 256;
    while (lo < hi) { int m = (lo + hi) >> 1; if (g[m] <= hiV) lo = m + 1; else hi = m; }
    int s1 = lo;
    float S = 0.0f;
    for (int i = s0; i < s1; i++) {
        float d = (g[i] - vb) * 100.0f;
        S += expf(-0.5f * d * d);
    }
    red[tid] = S;
    __syncthreads();
    for (int st = 128; st > 0; st >>= 1) { if (tid < st) red[tid] += red[tid + st]; __syncthreads(); }
    float T = red[0];
    __syncthreads();
    float p = fmaxf(S / T, 1e-10f);
    red[tid] = p * log2f(p);
    __syncthreads();
    for (int st = 128; st > 0; st >>= 1) { if (tid < st) red[tid] += red[tid + st]; __syncthreads(); }
    if (tid == 0) g_ent[bid] = -red[0];
}

__global__ void median_kernel()
{
    __shared__ float s[2048];
    int tid = threadIdx.x;
    s[tid] = g_ent[tid]; s[tid + 1024] = g_ent[tid + 1024];
    __syncthreads();
    for (int k = 2; k <= 2048; k <<= 1)
        for (int j = k >> 1; j > 0; j >>= 1) {
            for (int base = 0; base < 2048; base += 1024) {
                int i = base + tid, ixj = i ^ j;
                if (ixj > i) {
                    float a = s[i], c2 = s[ixj];
                    bool up = (i & k) == 0;
                    if ((a > c2) == up) { s[i] = c2; s[ixj] = a; }
                }
            }
            __syncthreads();
        }
    if (tid == 0) g_thr = 0.5f * (s[1023] + s[1024]);
}

__global__ void route_kernel(float* __restrict__ out, int write_aux)
{
    int i = blockIdx.x * blockDim.x + threadIdx.x;
    if (i >= 32768) return;
    float thr = g_thr;
    int n = i >> 12, c = (i >> 10) & 3, y = (i >> 5) & 31, xx = i & 31;
    int hp = y >> 1, wp = xx >> 1;
    float e = g_ent[n * 256 + hp * 16 + wp];
    float v = (e > thr) ? g_latf[i] : g_latc[((n * 4 + c) * 16 + hp) * 16 + wp];
    g_routed[i] = v;
    if (write_aux) {
        out[OFF_ROUTED + i] = v;
        if (i < 2048) {
            float ev = g_ent[i];
            out[OFF_GRAIN + i] = (ev > thr) ? 1.0f : 0.0f;
            out[OFF_ENT + i] = ev;
        }
    }
}

// -------- scalar conv Wi: 4->256 @32x32, no relu, OUT = padded NHWC bf16 hi/lo --------
__global__ __launch_bounds__(256, 2) void convWi_kernel(
    const float* __restrict__ in, const float* __restrict__ w,
    const float* __restrict__ bias, u16* __restrict__ oh, u16* __restrict__ ol)
{
    const int C_in = 4, H = 32, W = 32;
    __shared__ __align__(16) float s_in[4][18][20];
    __shared__ ull s_w2[4][9][64];
    int tiles_x = 2;
    int ty = blockIdx.x / tiles_x, tx = blockIdx.x - ty * tiles_x;
    int oc0 = blockIdx.y << 6, n = blockIdx.z;
    int y0 = ty << 4, x0 = tx << 4;
    int tid = threadIdx.x;
    int ocg = tid >> 4, pxg = tid & 15;
    int pr4 = (pxg >> 2) << 2, pc4 = (pxg & 3) << 2;
    ull acc[4][4][2];
    #pragma unroll
    for (int o = 0; o < 4; o++)
        #pragma unroll
        for (int r = 0; r < 4; r++) { acc[o][r][0] = 0; acc[o][r][1] = 0; }
    const float* in_n = in + (size_t)n * C_in * H * W;
    {
        __syncthreads();
        for (int e = tid; e < 4 * 324; e += 256) {
            int ic = e / 324, rem = e - ic * 324;
            int r = rem / 18, cc = rem - r * 18;
            int gy = y0 - 1 + r, gx = x0 - 1 + cc;
            float v = 0.0f;
            if ((unsigned)gy < (unsigned)H && (unsigned)gx < (unsigned)W)
                v = in_n[((size_t)ic * H + gy) * W + gx];
            s_in[ic][r][cc] = v;
        }
        for (int e = tid; e < 4 * 576; e += 256) {
            int ic = e / 576, rem = e - ic * 576;
            int k = rem >> 6, oc = rem & 63;
            s_w2[ic][k][oc] = bc2(w[((size_t)(oc0 + oc) * C_in + ic) * 9 + k]);
        }
        __syncthreads();
        #pragma unroll 1
        for (int ic = 0; ic < 4; ic++)
            #pragma unroll
            for (int ky = 0; ky < 3; ky++) {
                ull w2[3][4];
                #pragma unroll
                for (int kx = 0; kx < 3; kx++)
                    #pragma unroll
                    for (int o = 0; o < 4; o++) w2[kx][o] = s_w2[ic][ky * 3 + kx][(ocg << 2) + o];
                #pragma unroll
                for (int r = 0; r < 4; r++) {
                    const float* rp = &s_in[ic][pr4 + r + ky][pc4];
                    float4 v4 = *(const float4*)rp;
                    float2 v2 = *(const float2*)(rp + 4);
                    ull P0 = pk2(v4.x, v4.y), P1 = pk2(v4.y, v4.z), P2 = pk2(v4.z, v4.w);
                    ull P3 = pk2(v4.w, v2.x), P4 = pk2(v2.x, v2.y);
                    #pragma unroll
                    for (int o = 0; o < 4; o++) {
                        fma2(acc[o][r][0], w2[0][o], P0);
                        fma2(acc[o][r][1], w2[0][o], P2);
                        fma2(acc[o][r][0], w2[1][o], P1);
                        fma2(acc[o][r][1], w2[1][o], P3);
                        fma2(acc[o][r][0], w2[2][o], P2);
                        fma2(acc[o][r][1], w2[2][o], P4);
                    }
                }
            }
    }
    float bv[4];
    #pragma unroll
    for (int o = 0; o < 4; o++) bv[o] = bias[oc0 + (ocg << 2) + o];
    #pragma unroll
    for (int r = 0; r < 4; r++) {
        float vv[4][4];
        #pragma unroll
        for (int o = 0; o < 4; o++) {
            up2(vv[o][0], vv[o][1], acc[o][r][0]);
            up2(vv[o][2], vv[o][3], acc[o][r][1]);
            #pragma unroll
            for (int c = 0; c < 4; c++) vv[o][c] += bv[o];
        }
        int gy = y0 + pr4 + r + 1;
        #pragma unroll
        for (int c = 0; c < 4; c++) {
            u16 hv[4], lv[4];
            #pragma unroll
            for (int o = 0; o < 4; o++) {
                __nv_bfloat16 h = __float2bfloat16(vv[o][c]);
                hv[o] = __bfloat16_as_ushort(h);
                lv[o] = __bfloat16_as_ushort(__float2bfloat16(vv[o][c] - __bfloat162float(h)));
            }
            size_t off = ((size_t)(n * 34 + gy) * 34 + x0 + pc4 + c + 1) * 256 + oc0 + (ocg << 2);
            *(uint2*)&oh[off] = *(uint2*)hv;
            *(uint2*)&ol[off] = *(uint2*)lv;
        }
    }
}

// -------- Wo conv: 128->3, tanh (reads fp32 NCHW) --------
__global__ __launch_bounds__(256) void convWo_kernel(
    const float* __restrict__ in, const float* __restrict__ w,
    const float* __restrict__ bias, float* __restrict__ out)
{
    __shared__ float s_w[3456];
    __shared__ __align__(16) float s_in[2][10][260];
    int n = blockIdx.x >> 5;
    int y0 = (blockIdx.x & 31) << 3;
    int tid = threadIdx.x;
    int rowg = tid >> 6;
    int c4 = (tid & 63) << 2;
    for (int e = tid; e < 3456; e += 256) s_w[e] = w[e];
    ull acc[3][2][2];
    #pragma unroll
    for (int ch = 0; ch < 3; ch++)
        #pragma unroll
        for (int r = 0; r < 2; r++) { acc[ch][r][0] = 0; acc[ch][r][1] = 0; }
    const float* in_n = in + (size_t)n * 128 * 65536;
    for (int ic0 = 0; ic0 < 128; ic0 += 2) {
        __syncthreads();
        for (int e = tid; e < 2 * 2580; e += 256) {
            int ic = e / 2580, rem = e - ic * 2580;
            int rr = rem / 258, cc = rem - rr * 258;
            int gy = y0 - 1 + rr, gx = cc - 1;
            float v = 0.0f;
            if ((unsigned)gy < 256u && (unsigned)gx < 256u)
                v = in_n[(size_t)(ic0 + ic) * 65536 + gy * 256 + gx];
            s_in[ic][rr][cc] = v;
        }
        __syncthreads();
        #pragma unroll
        for (int ic = 0; ic < 2; ic++)
            #pragma unroll
            for (int ky = 0; ky < 3; ky++) {
                ull P[2][5];
                #pragma unroll
                for (int r = 0; r < 2; r++) {
                    const float* rp = &s_in[ic][(rowg << 1) + r + ky][c4];
                    float4 v4 = *(const float4*)rp;
                    float2 v2 = *(const float2*)(rp + 4);
                    P[r][0] = pk2(v4.x, v4.y); P[r][1] = pk2(v4.y, v4.z);
                    P[r][2] = pk2(v4.z, v4.w); P[r][3] = pk2(v4.w, v2.x);
                    P[r][4] = pk2(v2.x, v2.y);
                }
                #pragma unroll
                for (int kx = 0; kx < 3; kx++)
                    #pragma unroll
                    for (int ch = 0; ch < 3; ch++) {
                        ull wb = bc2(s_w[ch * 1152 + (ic0 + ic) * 9 + ky * 3 + kx]);
                        #pragma unroll
                        for (int r = 0; r < 2; r++) {
                            fma2(acc[ch][r][0], wb, P[r][kx]);
                            fma2(acc[ch][r][1], wb, P[r][kx + 2]);
                        }
                    }
            }
    }
    #pragma unroll
    for (int ch = 0; ch < 3; ch++) {
        float bv = bias[ch];
        #pragma unroll
        for (int r = 0; r < 2; r++) {
            int y = y0 + (rowg << 1) + r;
            float f0, f1, f2, f3;
            up2(f0, f1, acc[ch][r][0]); up2(f2, f3, acc[ch][r][1]);
            *(float4*)&out[((size_t)(n * 3 + ch) << 16) + y * 256 + c4] =
                make_float4(tanhf(f0 + bv), tanhf(f1 + bv), tanhf(f2 + bv), tanhf(f3 + bv));
        }
    }
}

// -------- MMA weight prep --------
__global__ void wprep_kernel(const float* __restrict__ w, int OC, int IC, int trans)
{
    int KC = IC >> 5;
    int tot = KC * 9 * OC * 32;
    u16* dst = (u16*)g_wscr;
    for (int idx = blockIdx.x * blockDim.x + threadIdx.x; idx < tot; idx += gridDim.x * blockDim.x) {
        int j = idx & 31;
        int t = idx >> 5;
        int oc = t % OC; t /= OC;
        int tap = t % 9;
        int kc = t / 9;
        float v = trans ? w[((size_t)(kc * 32 + j) * OC + oc) * 9 + tap]
                        : w[((size_t)oc * IC + kc * 32 + j) * 9 + tap];
        __nv_bfloat16 h = __float2bfloat16(v);
        __nv_bfloat16 l = __float2bfloat16(v - __bfloat162float(h));
        size_t b = ((((size_t)kc * 9 + tap) * 2 + 0) * OC + oc) * 32 + j;
        size_t b2 = ((((size_t)kc * 9 + tap) * 2 + 1) * OC + oc) * 32 + j;
        dst[b] = __bfloat16_as_ushort(h);
        dst[b2] = __bfloat16_as_ushort(l);
    }
}

// -------- pad-ring zero --------
__global__ void ring_kernel(u16* __restrict__ oh, u16* __restrict__ ol, int C, int H, int W)
{
    int Hp = H + 2, Wp = W + 2, IC8 = C >> 3;
    int per = (2 * Wp + 2 * H) * IC8;
    int tot = 8 * per;
    uint4 z = make_uint4(0, 0, 0, 0);
    uint4* h4 = (uint4*)oh;
    uint4* l4 = (uint4*)ol;
    for (int idx = blockIdx.x * blockDim.x + threadIdx.x; idx < tot; idx += gridDim.x * blockDim.x) {
        int n = idx / per, r = idx % per;
        int pix = r / IC8, c = r % IC8;
        int y, x;
        if (pix < Wp) { y = 0; x = pix; }
        else if (pix < 2 * Wp) { y = Hp - 1; x = pix - Wp; }
        else { int q = pix - 2 * Wp; y = 1 + (q >> 1); x = (q & 1) ? Wp - 1 : 0; }
        size_t o = ((size_t)(n * Hp + y) * Wp + x) * IC8 + c;
        h4[o] = z; l4[o] = z;
    }
}

// -------- mma.sync conv 3x3 s1 p1 (3-pass hi/lo), cp.async, R rows/block --------
template<int NT, int R>
__global__ __launch_bounds__(256) void conv_mma_kernel(
    const u16* __restrict__ xh, const u16* __restrict__ xl,
    const float* __restrict__ bias,
    float* __restrict__ outf, u16* __restrict__ oh, u16* __restrict__ ol,
    int KC, int H, int W, int OC, int IC, int mode)
{
    extern __shared__ __align__(16) u16 sm[];
    const int PX = NT * 16;
    int segs = W / PX;
    int yb = blockIdx.x / segs, x0 = (blockIdx.x % segs) * PX;
    int y0 = yb * R;
    int oc0 = blockIdx.y << 7, n = blockIdx.z;
    int tid = threadIdx.x, wid = tid >> 5, l = tid & 31;
    int ocg = wid & 3, pxg = wid >> 2;
    int Hp = H + 2, Wp = W + 2;
    uint32_t sbase = smem_u32(sm);
    const u16* gw = (const u16*)g_wscr;
    float d[2][R][NT][4];
    #pragma unroll
    for (int mt = 0; mt < 2; mt++)
        #pragma unroll
        for (int r = 0; r < R; r++)
            #pragma unroll
            for (int nt = 0; nt < NT; nt++)
                #pragma unroll
                for (int i = 0; i < 4; i++) d[mt][r][nt][i] = 0.0f;

    const int pc = (PX + 2) * 4;
    for (int kc = 0; kc < KC; kc++)
        for (int ky = 0; ky < 3; ky++) {
            __syncthreads();
            for (int e = tid; e < 3072; e += 256) {
                int j8 = e & 3, oc = (e >> 2) & 127, blk = e >> 9;
                int kx = blk % 3, hl = blk / 3;
                const uint4* src = (const uint4*)(gw +
                    ((((size_t)kc * 9 + ky * 3 + kx) * 2 + hl) * OC + oc0 + oc) * 32) + j8;
                CPA16(sbase + (uint32_t)(blk * 128 + oc) * 80 + j8 * 16, src);
            }
            for (int e = tid; e < R * 2 * pc; e += 256) {
                int r = e / (2 * pc);
                int e2 = e - r * 2 * pc;
                int hl = e2 >= pc; int rr = e2 - hl * pc;
                int p = rr >> 2, j8 = rr & 3;
                const u16* gx = hl ? xl : xh;
                const uint4* src = (const uint4*)(gx +
                    ((size_t)(n * Hp + y0 + r + ky) * Wp + x0 + p) * IC + (kc << 5)) + j8;
                CPA16(sbase + 61440u + (uint32_t)((r * 2 + hl) * (PX + 2) + p) * 80 + j8 * 16, src);
            }
            CP_COMMIT();
            CP_WAIT0();
            __syncthreads();
            for (int kx = 0; kx < 3; kx++)
                #pragma unroll
                for (int ks = 0; ks < 2; ks++) {
                    uint32_t Ah[2][4], Al[2][4];
                    #pragma unroll
                    for (int mt = 0; mt < 2; mt++) {
                        int row = ocg * 32 + mt * 16 + (l & 15);
                        uint32_t a = sbase + (uint32_t)(kx * 128 + row) * 80 + ks * 32 + (l >> 4) * 16;
                        LDSM4(Ah[mt], a);
                        LDSM4(Al[mt], a + 3 * 128 * 80);
                    }
                    #pragma unroll
                    for (int r = 0; r < R; r++) {
                        uint32_t Bh[NT][2], Bl[NT][2];
                        #pragma unroll
                        for (int nt = 0; nt < NT; nt++) {
                            int p = pxg * (NT * 8) + nt * 8 + (l & 7) + kx;
                            uint32_t b = sbase + 61440 + (uint32_t)((r * 2) * (PX + 2) + p) * 80
                                       + ks * 32 + (((l & 15) >> 3) * 16);
                            LDSM2(Bh[nt], b);
                            LDSM2(Bl[nt], b + (PX + 2) * 80);
                        }
                        #pragma unroll
                        for (int mt = 0; mt < 2; mt++)
                            #pragma unroll
                            for (int nt = 0; nt < NT; nt++) {
                                MMA(d[mt][r][nt], Ah[mt], Bh[nt]);
                                MMA(d[mt][r][nt], Ah[mt], Bl[nt]);
                                MMA(d[mt][r][nt], Al[mt], Bh[nt]);
                            }
                    }
                }
        }
    if (mode) {
        size_t plane = (size_t)H * W;
        #pragma unroll
        for (int mt = 0; mt < 2; mt++) {
            int ocr = oc0 + ocg * 32 + mt * 16 + (l >> 2);
            float b0 = bias[ocr], b8 = bias[ocr + 8];
            #pragma unroll
            for (int r = 0; r < R; r++) {
                float* ob = outf + ((size_t)n * OC + ocr) * plane + (size_t)(y0 + r) * W;
                #pragma unroll
                for (int nt = 0; nt < NT; nt++) {
                    int px = x0 + pxg * (NT * 8) + nt * 8 + (l & 3) * 2;
                    *(float2*)(ob + px) = make_float2(
                        fmaxf(d[mt][r][nt][0] + b0, 0.0f), fmaxf(d[mt][r][nt][1] + b0, 0.0f));
                    *(float2*)(ob + 8 * plane + px) = make_float2(
                        fmaxf(d[mt][r][nt][2] + b8, 0.0f), fmaxf(d[mt][r][nt][3] + b8, 0.0f));
                }
            }
        }
    } else {
        #pragma unroll
        for (int mt = 0; mt < 2; mt++) {
            int ocr = oc0 + ocg * 32 + mt * 16 + (l >> 2);
            float b0 = bias[ocr], b8 = bias[ocr + 8];
            #pragma unroll
            for (int r = 0; r < R; r++)
                #pragma unroll
                for (int nt = 0; nt < NT; nt++) {
                    int px = x0 + pxg * (NT * 8) + nt * 8 + (l & 3) * 2;
                    size_t base2 = ((size_t)(n * Hp + y0 + r + 1) * Wp + px + 1) * OC;
                    stsplit(oh, ol, base2 + ocr,          fmaxf(d[mt][r][nt][0] + b0, 0.0f));
                    stsplit(oh, ol, base2 + OC + ocr,     fmaxf(d[mt][r][nt][1] + b0, 0.0f));
                    stsplit(oh, ol, base2 + ocr + 8,      fmaxf(d[mt][r][nt][2] + b8, 0.0f));
                    stsplit(oh, ol, base2 + OC + ocr + 8, fmaxf(d[mt][r][nt][3] + b8, 0.0f));
                }
        }
    }
}

// -------- mma.sync DECONV k3 s2 p1 op1 + relu, cp.async --------
// ky=1 and ky=2 read the same input row (y+1): pixel staging skipped at ky==2.
template<int NT>
__global__ __launch_bounds__(256) void deconv_mma_kernel(
    const u16* __restrict__ xh, const u16* __restrict__ xl,
    u16* __restrict__ oh, u16* __restrict__ ol,
    const float* __restrict__ bias,
    int KC, int H, int W, int OC, int IC)
{
    extern __shared__ __align__(16) u16 sm[];
    const int PX = NT * 16;
    int segs = W / PX;
    int y = blockIdx.x / segs, x0 = (blockIdx.x % segs) * PX;
    int oc0 = blockIdx.y << 7, n = blockIdx.z;
    int tid = threadIdx.x, wid = tid >> 5, l = tid & 31;
    int ocg = wid & 3, pxg = wid >> 2;
    int Hp = H + 2, Wp = W + 2;
    uint32_t sbase = smem_u32(sm);
    const u16* gw = (const u16*)g_wscr;
    float d[2][2][2][NT][4];                 // [mt][dy][dx][nt][4]
    #pragma unroll
    for (int mt = 0; mt < 2; mt++)
        #pragma unroll
        for (int a = 0; a < 2; a++)
            #pragma unroll
            for (int b = 0; b < 2; b++)
                #pragma unroll
                for (int nt = 0; nt < NT; nt++)
                    #pragma unroll
                    for (int i = 0; i < 4; i++) d[mt][a][b][nt][i] = 0.0f;

    const int pcd = (PX + 1) * 4;
    for (int kc = 0; kc < KC; kc++)
        for (int ky = 0; ky < 3; ky++) {
            __syncthreads();
            for (int e = tid; e < 3072; e += 256) {
                int j8 = e & 3, oc = (e >> 2) & 127, blk = e >> 9;
                int kx = blk % 3, hl = blk / 3;
                const uint4* src = (const uint4*)(gw +
                    ((((size_t)kc * 9 + ky * 3 + kx) * 2 + hl) * OC + oc0 + oc) * 32) + j8;
                CPA16(sbase + (uint32_t)(blk * 128 + oc) * 80 + j8 * 16, src);
            }
            if (ky != 2) {                   // ky==2 reuses ky==1's pixel row (y+1)
                int ry = y + 1 + (ky == 0);  // padded input row
                for (int e = tid; e < 2 * pcd; e += 256) {
                    int hl = e >= pcd; int r = e - hl * pcd;
                    int p = r >> 2, j8 = r & 3;
                    const u16* gx = hl ? xl : xh;
                    const uint4* src = (const uint4*)(gx +
                        ((size_t)(n * Hp + ry) * Wp + x0 + 1 + p) * IC + (kc << 5)) + j8;
                    CPA16(sbase + 61440u + (uint32_t)(hl * (PX + 1) + p) * 80 + j8 * 16, src);
                }
            }
            CP_COMMIT();
            CP_WAIT0();
            __syncthreads();
            int dy = (ky != 1);
            #pragma unroll
            for (int ks = 0; ks < 2; ks++) {
                uint32_t Bf[2][2][NT][2];    // [hl][shift][nt][2]
                #pragma unroll
                for (int sh = 0; sh < 2; sh++)
                    #pragma unroll
                    for (int nt = 0; nt < NT; nt++) {
                        int p = pxg * (NT * 8) + nt * 8 + (l & 7) + sh;
                        uint32_t b = sbase + 61440 + (uint32_t)p * 80 + ks * 32 + (((l & 15) >> 3) * 16);
                        LDSM2(Bf[0][sh][nt], b);
                        LDSM2(Bf[1][sh][nt], b + (PX + 1) * 80);
                    }
                for (int kx = 0; kx < 3; kx++) {
                    int sh = (kx == 0), dxp = (kx != 1);
                    uint32_t Ah[2][4], Al[2][4];
                    #pragma unroll
                    for (int mt = 0; mt < 2; mt++) {
                        int row = ocg * 32 + mt * 16 + (l & 15);
                        uint32_t a = sbase + (uint32_t)(kx * 128 + row) * 80 + ks * 32 + (l >> 4) * 16;
                        LDSM4(Ah[mt], a);
                        LDSM4(Al[mt], a + 3 * 128 * 80);
                    }
                    #pragma unroll
                    for (int mt = 0; mt < 2; mt++)
                        #pragma unroll
                        for (int nt = 0; nt < NT; nt++) {
                            MMA(d[mt][dy][dxp][nt], Ah[mt], Bf[0][sh][nt]);
                            MMA(d[mt][dy][dxp][nt], Ah[mt], Bf[1][sh][nt]);
                            MMA(d[mt][dy][dxp][nt], Al[mt], Bf[0][sh][nt]);
                        }
                }
            }
        }
    int OHp = 2 * H + 2, OWp = 2 * W + 2;
    #pragma unroll
    for (int mt = 0; mt < 2; mt++) {
        int ocr = oc0 + ocg * 32 + mt * 16 + (l >> 2);
        float b0 = bias[ocr], b8 = bias[ocr + 8];
        #pragma unroll
        for (int dy2 = 0; dy2 < 2; dy2++)
            #pragma unroll
            for (int dxp = 0; dxp < 2; dxp++)
                #pragma unroll
                for (int nt = 0; nt < NT; nt++) {
                    int p0 = x0 + pxg * (NT * 8) + nt * 8 + 2 * (l & 3);
                    size_t base2 = ((size_t)(n * OHp + 2 * y + dy2 + 1) * OWp + 2 * p0 + dxp + 1) * OC;
                    stsplit(oh, ol, base2 + ocr,              fmaxf(d[mt][dy2][dxp][nt][0] + b0, 0.0f));
                    stsplit(oh, ol, base2 + 2 * OC + ocr,     fmaxf(d[mt][dy2][dxp][nt][1] + b0, 0.0f));
                    stsplit(oh, ol, base2 + ocr + 8,          fmaxf(d[mt][dy2][dxp][nt][2] + b8, 0.0f));
                    stsplit(oh, ol, base2 + 2 * OC + ocr + 8, fmaxf(d[mt][dy2][dxp][nt][3] + b8, 0.0f));
                }
    }
}

// -------- host --------
static void conv_mma(const float* w, const float* b, const u16* xh, const u16* xl,
                     u16* oh, u16* ol, float* outf, int IC, int OC, int H, int W, int mode)
{
    wprep_kernel<<<128, 256>>>(w, OC, IC, 0);
    if (mode == 0) ring_kernel<<<256, 256>>>(oh, ol, OC, H, W);
    if (W >= 128) {
        dim3 grid((W / 128) * (H / 2), OC / 128, 8);
        conv_mma_kernel<8, 2><<<grid, 256, 61440 + 2 * 2 * 130 * 80>>>(
            xh, xl, b, outf, oh, ol, IC / 32, H, W, OC, IC, mode);
    } else {
        dim3 grid((W / 64) * (H / 2), OC / 128, 8);
        conv_mma_kernel<4, 2><<<grid, 256, 61440 + 2 * 2 * 66 * 80>>>(
            xh, xl, b, outf, oh, ol, IC / 32, H, W, OC, IC, mode);
    }
}

static void deconv_mma(const float* w, const float* b, const u16* xh, const u16* xl,
                       u16* oh, u16* ol, int IC, int OC, int H, int W)
{
    wprep_kernel<<<128, 256>>>(w, OC, IC, 1);
    ring_kernel<<<256, 256>>>(oh, ol, OC, 2 * H, 2 * W);
    if (W >= 64) {
        dim3 grid((W / 64) * H, OC / 128, 8);
        deconv_mma_kernel<4><<<grid, 256, 61440 + 2 * 65 * 80>>>(
            xh, xl, oh, ol, b, IC / 32, H, W, OC, IC);
    } else {
        dim3 grid((W / 32) * H, OC / 128, 8);
        deconv_mma_kernel<2><<<grid, 256, 61440 + 2 * 33 * 80>>>(
            xh, xl, oh, ol, b, IC / 32, H, W, OC, IC);
    }
}

extern "C" void kernel_launch(void* const* d_in, const int* in_sizes, int n_in,
                              void* d_out, int out_size)
{
    const float* x   = (const float*)d_in[0];
    const float* We0 = (const float*)d_in[1];
    const float* be0 = (const float*)d_in[2];
    const float* We1 = (const float*)d_in[3];
    const float* be1 = (const float*)d_in[4];
    const float* Wi  = (const float*)d_in[5];
    const float* bi  = (const float*)d_in[6];
    const float* Wd1 = (const float*)d_in[7];
    const float* bd1 = (const float*)d_in[8];
    const float* Wc1 = (const float*)d_in[9];
    const float* bc1 = (const float*)d_in[10];
    const float* Wd2 = (const float*)d_in[11];
    const float* bd2 = (const float*)d_in[12];
    const float* Wc2 = (const float*)d_in[13];
    const float* bc2_ = (const float*)d_in[14];
    const float* Wd3 = (const float*)d_in[15];
    const float* bd3 = (const float*)d_in[16];
    const float* Wc3 = (const float*)d_in[17];
    const float* bc3 = (const float*)d_in[18];
    const float* Wo  = (const float*)d_in[19];
    const float* bo  = (const float*)d_in[20];
    float* out = (float*)d_out;

    static int once = 0;
    if (!once) {
        cudaFuncSetAttribute(conv_mma_kernel<8, 2>, cudaFuncAttributeMaxDynamicSharedMemorySize, 104000);
        cudaFuncSetAttribute(conv_mma_kernel<4, 2>, cudaFuncAttributeMaxDynamicSharedMemorySize, 104000);
        cudaFuncSetAttribute(deconv_mma_kernel<4>, cudaFuncAttributeMaxDynamicSharedMemorySize, 104000);
        cudaFuncSetAttribute(deconv_mma_kernel<2>, cudaFuncAttributeMaxDynamicSharedMemorySize, 104000);
        once = 1;
    }

    float *h3buf, *routed;
    u16 *pAh, *pAl, *pBh, *pBl;
    cudaGetSymbolAddress((void**)&h3buf, g_bufA);
    cudaGetSymbolAddress((void**)&routed, g_routed);
    cudaGetSymbolAddress((void**)&pAh, g_pAh);
    cudaGetSymbolAddress((void**)&pAl, g_pAl);
    cudaGetSymbolAddress((void**)&pBh, g_pBh);
    cudaGetSymbolAddress((void**)&pBl, g_pBl);

    encoder_kernel<<<160, 256>>>(x, We0, be0, We1, be1);
    entropy_kernel<<<2048, 256>>>(x);
    median_kernel<<<1, 1024>>>();
    int write_aux = (out_size >= OUT_FULL) ? 1 : 0;
    route_kernel<<<128, 256>>>(out, write_aux);

    ring_kernel<<<256, 256>>>(pAh, pAl, 256, 32, 32);
    dim3 gWi(4, 4, 8);
    convWi_kernel<<<gWi, 256>>>(routed, Wi, bi, pAh, pAl);
    deconv_mma(Wd1, bd1, pAh, pAl, pBh, pBl, 256, 256, 32, 32);
    conv_mma(Wc1, bc1, pBh, pBl, pAh, pAl, nullptr, 256, 256, 64, 64, 0);
    deconv_mma(Wd2, bd2, pAh, pAl, pBh, pBl, 256, 128, 64, 64);
    conv_mma(Wc2, bc2_, pBh, pBl, pAh, pAl, nullptr, 128, 128, 128, 128, 0);
    deconv_mma(Wd3, bd3, pAh, pAl, pBh, pBl, 128, 128, 128, 128);
    conv_mma(Wc3, bc3, pBh, pBl, nullptr, nullptr, h3buf, 128, 128, 256, 256, 1);
    convWo_kernel<<<256, 256>>>(h3buf, Wo, bo, out);
}

// round 14
// speedup vs baseline: 1.8724x; 1.0188x over previous
#include <cuda_runtime.h>
#include <cuda_bf16.h>
#include <math.h>
#include <stdint.h>

typedef unsigned long long ull;
typedef unsigned short u16;

__device__ __forceinline__ ull pk2(float lo, float hi) {
    ull r; asm("mov.b64 %0, {%1, %2};" : "=l"(r) : "f"(lo), "f"(hi)); return r;
}
__device__ __forceinline__ ull bc2(float v) {
    ull r; asm("mov.b64 %0, {%1, %1};" : "=l"(r) : "f"(v)); return r;
}
__device__ __forceinline__ void fma2(ull& d, ull a, ull b) {
    asm("fma.rn.f32x2 %0, %1, %2, %0;" : "+l"(d) : "l"(a), "l"(b));
}
__device__ __forceinline__ void up2(float& lo, float& hi, ull v) {
    asm("mov.b64 {%0, %1}, %2;" : "=f"(lo), "=f"(hi) : "l"(v));
}
__device__ __forceinline__ uint32_t smem_u32(const void* p) {
    uint32_t a;
    asm("{ .reg .u64 t; cvta.to.shared.u64 t, %1; cvt.u32.u64 %0, t; }" : "=r"(a) : "l"(p));
    return a;
}
__device__ __forceinline__ void stsplit(u16* __restrict__ oh, u16* __restrict__ ol,
                                        size_t o, float v)
{
    __nv_bfloat16 h = __float2bfloat16(v);
    oh[o] = __bfloat16_as_ushort(h);
    ol[o] = __bfloat16_as_ushort(__float2bfloat16(v - __bfloat162float(h)));
}
#define CPA16(dst, src) asm volatile( \
    "cp.async.ca.shared.global [%0], [%1], 16;" :: "r"(dst), "l"(src))
#define CP_COMMIT() asm volatile("cp.async.commit_group;" ::: "memory")
#define CP_WAIT0() asm volatile("cp.async.wait_group 0;" ::: "memory")
#define LDSM4(R, a) asm volatile( \
    "ldmatrix.sync.aligned.m8n8.x4.shared.b16 {%0,%1,%2,%3},[%4];" \
    : "=r"((R)[0]), "=r"((R)[1]), "=r"((R)[2]), "=r"((R)[3]) : "r"(a))
#define LDSM4S(r0, r1, r2, r3, a) asm volatile( \
    "ldmatrix.sync.aligned.m8n8.x4.shared.b16 {%0,%1,%2,%3},[%4];" \
    : "=r"(r0), "=r"(r1), "=r"(r2), "=r"(r3) : "r"(a))
#define MMA(D, A, B) asm volatile( \
    "mma.sync.aligned.m16n8k16.row.col.f32.bf16.bf16.f32 " \
    "{%0,%1,%2,%3},{%4,%5,%6,%7},{%8,%9},{%0,%1,%2,%3};" \
    : "+f"((D)[0]), "+f"((D)[1]), "+f"((D)[2]), "+f"((D)[3]) \
    : "r"((A)[0]), "r"((A)[1]), "r"((A)[2]), "r"((A)[3]), "r"((B)[0]), "r"((B)[1]))

// -------- scratch globals --------
__device__ float g_bufA[67200000];   // h3 fp32 NCHW
__device__ u16 g_pAh[70000000];      // ping NHWC bf16 hi (padded)
__device__ u16 g_pAl[70000000];
__device__ u16 g_pBh[70000000];      // pong
__device__ u16 g_pBl[70000000];
__device__ uint4 g_wscr[150000];     // [kc32][tap][hl][oc][32] bf16
__device__ float g_latf[32768];
__device__ float g_latc[8192];
__device__ float g_ent[2048];
__device__ float g_routed[32768];
__device__ float g_thr;

#define OFF_ROUTED 1572864
#define OFF_GRAIN  1605632
#define OFF_ENT    1607680
#define OUT_FULL   1609728

// -------- encoder --------
__global__ void encoder_kernel(const float* __restrict__ x,
                               const float* __restrict__ We0, const float* __restrict__ be0,
                               const float* __restrict__ We1, const float* __restrict__ be1)
{
    int idx = blockIdx.x * blockDim.x + threadIdx.x;
    if (idx < 32768) {
        int n = idx >> 12, c = (idx >> 10) & 3, oy = (idx >> 5) & 31, ox = idx & 31;
        float acc = be0[c];
        for (int ic = 0; ic < 3; ic++)
            for (int ky = 0; ky < 3; ky++) {
                int iy = oy * 8 - 1 + ky;
                if ((unsigned)iy >= 256u) continue;
                for (int kx = 0; kx < 3; kx++) {
                    int ix = ox * 8 - 1 + kx;
                    if ((unsigned)ix >= 256u) continue;
                    acc += x[((n * 3 + ic) * 256 + iy) * 256 + ix] *
                           We0[((c * 3 + ic) * 3 + ky) * 3 + kx];
                }
            }
        g_latf[idx] = acc;
    } else if (idx < 40960) {
        int i2 = idx - 32768;
        int n = i2 >> 10, c = (i2 >> 8) & 3, oy = (i2 >> 4) & 15, ox = i2 & 15;
        float acc = be1[c];
        for (int ic = 0; ic < 3; ic++)
            for (int ky = 0; ky < 3; ky++) {
                int iy = oy * 16 - 1 + ky;
                if ((unsigned)iy >= 256u) continue;
                for (int kx = 0; kx < 3; kx++) {
                    int ix = ox * 16 - 1 + kx;
                    if ((unsigned)ix >= 256u) continue;
                    acc += x[((n * 3 + ic) * 256 + iy) * 256 + ix] *
                           We1[((c * 3 + ic) * 3 + ky) * 3 + kx];
                }
            }
        g_latc[i2] = acc;
    }
}

// -------- entropy / median / route --------
__global__ void entropy_kernel(const float* __restrict__ x)
{
    __shared__ float g[256];
    __shared__ float red[256];
    int bid = blockIdx.x;
    int b = bid >> 8, hp = (bid >> 4) & 15, wp = bid & 15;
    int tid = threadIdx.x;
    int gy = hp * 16 + (tid >> 4), gx = wp * 16 + (tid & 15);
    const float* xb = x + (size_t)b * 3 * 65536;
    g[tid] = 0.299f * xb[gy * 256 + gx] + 0.587f * xb[65536 + gy * 256 + gx]
           + 0.114f * xb[131072 + gy * 256 + gx];
    __syncthreads();
    for (int k = 2; k <= 256; k <<= 1)
        for (int j = k >> 1; j > 0; j >>= 1) {
            int ixj = tid ^ j;
            if (ixj > tid) {
                float a = g[tid], c2 = g[ixj];
                bool up = (tid & k) == 0;
                if ((a > c2) == up) { g[tid] = c2; g[ixj] = a; }
            }
            __syncthreads();
        }
    float vb = tid * (1.0f / 255.0f);
    float loV = vb - 0.0945f, hiV = vb + 0.0945f;
    int lo = 0, hi = 256;
    while (lo < hi) { int m = (lo + hi) >> 1; if (g[m] < loV) lo = m + 1; else hi = m; }
    int s0 = lo;
    lo = s0; hi = 256;
    while (lo < hi) { int m = (lo + hi) >> 1; if (g[m] <= hiV) lo = m + 1; else hi = m; }
    int s1 = lo;
    float S = 0.0f;
    for (int i = s0; i < s1; i++) {
        float d = (g[i] - vb) * 100.0f;
        S += expf(-0.5f * d * d);
    }
    red[tid] = S;
    __syncthreads();
    for (int st = 128; st > 0; st >>= 1) { if (tid < st) red[tid] += red[tid + st]; __syncthreads(); }
    float T = red[0];
    __syncthreads();
    float p = fmaxf(S / T, 1e-10f);
    red[tid] = p * log2f(p);
    __syncthreads();
    for (int st = 128; st > 0; st >>= 1) { if (tid < st) red[tid] += red[tid + st]; __syncthreads(); }
    if (tid == 0) g_ent[bid] = -red[0];
}

__global__ void median_kernel()
{
    __shared__ float s[2048];
    int tid = threadIdx.x;
    s[tid] = g_ent[tid]; s[tid + 1024] = g_ent[tid + 1024];
    __syncthreads();
    for (int k = 2; k <= 2048; k <<= 1)
        for (int j = k >> 1; j > 0; j >>= 1) {
            for (int base = 0; base < 2048; base += 1024) {
                int i = base + tid, ixj = i ^ j;
                if (ixj > i) {
                    float a = s[i], c2 = s[ixj];
                    bool up = (i & k) == 0;
                    if ((a > c2) == up) { s[i] = c2; s[ixj] = a; }
                }
            }
            __syncthreads();
        }
    if (tid == 0) g_thr = 0.5f * (s[1023] + s[1024]);
}

__global__ void route_kernel(float* __restrict__ out, int write_aux)
{
    int i = blockIdx.x * blockDim.x + threadIdx.x;
    if (i >= 32768) return;
    float thr = g_thr;
    int n = i >> 12, c = (i >> 10) & 3, y = (i >> 5) & 31, xx = i & 31;
    int hp = y >> 1, wp = xx >> 1;
    float e = g_ent[n * 256 + hp * 16 + wp];
    float v = (e > thr) ? g_latf[i] : g_latc[((n * 4 + c) * 16 + hp) * 16 + wp];
    g_routed[i] = v;
    if (write_aux) {
        out[OFF_ROUTED + i] = v;
        if (i < 2048) {
            float ev = g_ent[i];
            out[OFF_GRAIN + i] = (ev > thr) ? 1.0f : 0.0f;
            out[OFF_ENT + i] = ev;
        }
    }
}

// -------- scalar conv Wi: 4->256 @32x32, no relu, OUT = padded NHWC bf16 hi/lo --------
__global__ __launch_bounds__(256, 2) void convWi_kernel(
    const float* __restrict__ in, const float* __restrict__ w,
    const float* __restrict__ bias, u16* __restrict__ oh, u16* __restrict__ ol)
{
    const int C_in = 4, H = 32, W = 32;
    __shared__ __align__(16) float s_in[4][18][20];
    __shared__ ull s_w2[4][9][64];
    int tiles_x = 2;
    int ty = blockIdx.x / tiles_x, tx = blockIdx.x - ty * tiles_x;
    int oc0 = blockIdx.y << 6, n = blockIdx.z;
    int y0 = ty << 4, x0 = tx << 4;
    int tid = threadIdx.x;
    int ocg = tid >> 4, pxg = tid & 15;
    int pr4 = (pxg >> 2) << 2, pc4 = (pxg & 3) << 2;
    ull acc[4][4][2];
    #pragma unroll
    for (int o = 0; o < 4; o++)
        #pragma unroll
        for (int r = 0; r < 4; r++) { acc[o][r][0] = 0; acc[o][r][1] = 0; }
    const float* in_n = in + (size_t)n * C_in * H * W;
    {
        __syncthreads();
        for (int e = tid; e < 4 * 324; e += 256) {
            int ic = e / 324, rem = e - ic * 324;
            int r = rem / 18, cc = rem - r * 18;
            int gy = y0 - 1 + r, gx = x0 - 1 + cc;
            float v = 0.0f;
            if ((unsigned)gy < (unsigned)H && (unsigned)gx < (unsigned)W)
                v = in_n[((size_t)ic * H + gy) * W + gx];
            s_in[ic][r][cc] = v;
        }
        for (int e = tid; e < 4 * 576; e += 256) {
            int ic = e / 576, rem = e - ic * 576;
            int k = rem >> 6, oc = rem & 63;
            s_w2[ic][k][oc] = bc2(w[((size_t)(oc0 + oc) * C_in + ic) * 9 + k]);
        }
        __syncthreads();
        #pragma unroll 1
        for (int ic = 0; ic < 4; ic++)
            #pragma unroll
            for (int ky = 0; ky < 3; ky++) {
                ull w2[3][4];
                #pragma unroll
                for (int kx = 0; kx < 3; kx++)
                    #pragma unroll
                    for (int o = 0; o < 4; o++) w2[kx][o] = s_w2[ic][ky * 3 + kx][(ocg << 2) + o];
                #pragma unroll
                for (int r = 0; r < 4; r++) {
                    const float* rp = &s_in[ic][pr4 + r + ky][pc4];
                    float4 v4 = *(const float4*)rp;
                    float2 v2 = *(const float2*)(rp + 4);
                    ull P0 = pk2(v4.x, v4.y), P1 = pk2(v4.y, v4.z), P2 = pk2(v4.z, v4.w);
                    ull P3 = pk2(v4.w, v2.x), P4 = pk2(v2.x, v2.y);
                    #pragma unroll
                    for (int o = 0; o < 4; o++) {
                        fma2(acc[o][r][0], w2[0][o], P0);
                        fma2(acc[o][r][1], w2[0][o], P2);
                        fma2(acc[o][r][0], w2[1][o], P1);
                        fma2(acc[o][r][1], w2[1][o], P3);
                        fma2(acc[o][r][0], w2[2][o], P2);
                        fma2(acc[o][r][1], w2[2][o], P4);
                    }
                }
            }
    }
    float bv[4];
    #pragma unroll
    for (int o = 0; o < 4; o++) bv[o] = bias[oc0 + (ocg << 2) + o];
    #pragma unroll
    for (int r = 0; r < 4; r++) {
        float vv[4][4];
        #pragma unroll
        for (int o = 0; o < 4; o++) {
            up2(vv[o][0], vv[o][1], acc[o][r][0]);
            up2(vv[o][2], vv[o][3], acc[o][r][1]);
            #pragma unroll
            for (int c = 0; c < 4; c++) vv[o][c] += bv[o];
        }
        int gy = y0 + pr4 + r + 1;
        #pragma unroll
        for (int c = 0; c < 4; c++) {
            u16 hv[4], lv[4];
            #pragma unroll
            for (int o = 0; o < 4; o++) {
                __nv_bfloat16 h = __float2bfloat16(vv[o][c]);
                hv[o] = __bfloat16_as_ushort(h);
                lv[o] = __bfloat16_as_ushort(__float2bfloat16(vv[o][c] - __bfloat162float(h)));
            }
            size_t off = ((size_t)(n * 34 + gy) * 34 + x0 + pc4 + c + 1) * 256 + oc0 + (ocg << 2);
            *(uint2*)&oh[off] = *(uint2*)hv;
            *(uint2*)&ol[off] = *(uint2*)lv;
        }
    }
}

// -------- Wo conv: 128->3, tanh (reads fp32 NCHW) --------
__global__ __launch_bounds__(256) void convWo_kernel(
    const float* __restrict__ in, const float* __restrict__ w,
    const float* __restrict__ bias, float* __restrict__ out)
{
    __shared__ float s_w[3456];
    __shared__ __align__(16) float s_in[2][10][260];
    int n = blockIdx.x >> 5;
    int y0 = (blockIdx.x & 31) << 3;
    int tid = threadIdx.x;
    int rowg = tid >> 6;
    int c4 = (tid & 63) << 2;
    for (int e = tid; e < 3456; e += 256) s_w[e] = w[e];
    ull acc[3][2][2];
    #pragma unroll
    for (int ch = 0; ch < 3; ch++)
        #pragma unroll
        for (int r = 0; r < 2; r++) { acc[ch][r][0] = 0; acc[ch][r][1] = 0; }
    const float* in_n = in + (size_t)n * 128 * 65536;
    for (int ic0 = 0; ic0 < 128; ic0 += 2) {
        __syncthreads();
        for (int e = tid; e < 2 * 2580; e += 256) {
            int ic = e / 2580, rem = e - ic * 2580;
            int rr = rem / 258, cc = rem - rr * 258;
            int gy = y0 - 1 + rr, gx = cc - 1;
            float v = 0.0f;
            if ((unsigned)gy < 256u && (unsigned)gx < 256u)
                v = in_n[(size_t)(ic0 + ic) * 65536 + gy * 256 + gx];
            s_in[ic][rr][cc] = v;
        }
        __syncthreads();
        #pragma unroll
        for (int ic = 0; ic < 2; ic++)
            #pragma unroll
            for (int ky = 0; ky < 3; ky++) {
                ull P[2][5];
                #pragma unroll
                for (int r = 0; r < 2; r++) {
                    const float* rp = &s_in[ic][(rowg << 1) + r + ky][c4];
                    float4 v4 = *(const float4*)rp;
                    float2 v2 = *(const float2*)(rp + 4);
                    P[r][0] = pk2(v4.x, v4.y); P[r][1] = pk2(v4.y, v4.z);
                    P[r][2] = pk2(v4.z, v4.w); P[r][3] = pk2(v4.w, v2.x);
                    P[r][4] = pk2(v2.x, v2.y);
                }
                #pragma unroll
                for (int kx = 0; kx < 3; kx++)
                    #pragma unroll
                    for (int ch = 0; ch < 3; ch++) {
                        ull wb = bc2(s_w[ch * 1152 + (ic0 + ic) * 9 + ky * 3 + kx]);
                        #pragma unroll
                        for (int r = 0; r < 2; r++) {
                            fma2(acc[ch][r][0], wb, P[r][kx]);
                            fma2(acc[ch][r][1], wb, P[r][kx + 2]);
                        }
                    }
            }
    }
    #pragma unroll
    for (int ch = 0; ch < 3; ch++) {
        float bv = bias[ch];
        #pragma unroll
        for (int r = 0; r < 2; r++) {
            int y = y0 + (rowg << 1) + r;
            float f0, f1, f2, f3;
            up2(f0, f1, acc[ch][r][0]); up2(f2, f3, acc[ch][r][1]);
            *(float4*)&out[((size_t)(n * 3 + ch) << 16) + y * 256 + c4] =
                make_float4(tanhf(f0 + bv), tanhf(f1 + bv), tanhf(f2 + bv), tanhf(f3 + bv));
        }
    }
}

// -------- MMA weight prep --------
__global__ void wprep_kernel(const float* __restrict__ w, int OC, int IC, int trans)
{
    int KC = IC >> 5;
    int tot = KC * 9 * OC * 32;
    u16* dst = (u16*)g_wscr;
    for (int idx = blockIdx.x * blockDim.x + threadIdx.x; idx < tot; idx += gridDim.x * blockDim.x) {
        int j = idx & 31;
        int t = idx >> 5;
        int oc = t % OC; t /= OC;
        int tap = t % 9;
        int kc = t / 9;
        float v = trans ? w[((size_t)(kc * 32 + j) * OC + oc) * 9 + tap]
                        : w[((size_t)oc * IC + kc * 32 + j) * 9 + tap];
        __nv_bfloat16 h = __float2bfloat16(v);
        __nv_bfloat16 l = __float2bfloat16(v - __bfloat162float(h));
        size_t b = ((((size_t)kc * 9 + tap) * 2 + 0) * OC + oc) * 32 + j;
        size_t b2 = ((((size_t)kc * 9 + tap) * 2 + 1) * OC + oc) * 32 + j;
        dst[b] = __bfloat16_as_ushort(h);
        dst[b2] = __bfloat16_as_ushort(l);
    }
}

// -------- pad-ring zero --------
__global__ void ring_kernel(u16* __restrict__ oh, u16* __restrict__ ol, int C, int H, int W)
{
    int Hp = H + 2, Wp = W + 2, IC8 = C >> 3;
    int per = (2 * Wp + 2 * H) * IC8;
    int tot = 8 * per;
    uint4 z = make_uint4(0, 0, 0, 0);
    uint4* h4 = (uint4*)oh;
    uint4* l4 = (uint4*)ol;
    for (int idx = blockIdx.x * blockDim.x + threadIdx.x; idx < tot; idx += gridDim.x * blockDim.x) {
        int n = idx / per, r = idx % per;
        int pix = r / IC8, c = r % IC8;
        int y, x;
        if (pix < Wp) { y = 0; x = pix; }
        else if (pix < 2 * Wp) { y = Hp - 1; x = pix - Wp; }
        else { int q = pix - 2 * Wp; y = 1 + (q >> 1); x = (q & 1) ? Wp - 1 : 0; }
        size_t o = ((size_t)(n * Hp + y) * Wp + x) * IC8 + c;
        h4[o] = z; l4[o] = z;
    }
}

// -------- mma.sync conv 3x3 s1 p1 (3-pass hi/lo), cp.async, R rows/block --------
// B fragments loaded pairwise via ldmatrix.x4 (lanes 16-31 -> nt+1).
template<int NT, int R>
__global__ __launch_bounds__(256) void conv_mma_kernel(
    const u16* __restrict__ xh, const u16* __restrict__ xl,
    const float* __restrict__ bias,
    float* __restrict__ outf, u16* __restrict__ oh, u16* __restrict__ ol,
    int KC, int H, int W, int OC, int IC, int mode)
{
    extern __shared__ __align__(16) u16 sm[];
    const int PX = NT * 16;
    int segs = W / PX;
    int yb = blockIdx.x / segs, x0 = (blockIdx.x % segs) * PX;
    int y0 = yb * R;
    int oc0 = blockIdx.y << 7, n = blockIdx.z;
    int tid = threadIdx.x, wid = tid >> 5, l = tid & 31;
    int ocg = wid & 3, pxg = wid >> 2;
    int Hp = H + 2, Wp = W + 2;
    uint32_t sbase = smem_u32(sm);
    const u16* gw = (const u16*)g_wscr;
    float d[2][R][NT][4];
    #pragma unroll
    for (int mt = 0; mt < 2; mt++)
        #pragma unroll
        for (int r = 0; r < R; r++)
            #pragma unroll
            for (int nt = 0; nt < NT; nt++)
                #pragma unroll
                for (int i = 0; i < 4; i++) d[mt][r][nt][i] = 0.0f;

    const int pc = (PX + 2) * 4;
    for (int kc = 0; kc < KC; kc++)
        for (int ky = 0; ky < 3; ky++) {
            __syncthreads();
            for (int e = tid; e < 3072; e += 256) {
                int j8 = e & 3, oc = (e >> 2) & 127, blk = e >> 9;
                int kx = blk % 3, hl = blk / 3;
                const uint4* src = (const uint4*)(gw +
                    ((((size_t)kc * 9 + ky * 3 + kx) * 2 + hl) * OC + oc0 + oc) * 32) + j8;
                CPA16(sbase + (uint32_t)(blk * 128 + oc) * 80 + j8 * 16, src);
            }
            for (int e = tid; e < R * 2 * pc; e += 256) {
                int r = e / (2 * pc);
                int e2 = e - r * 2 * pc;
                int hl = e2 >= pc; int rr = e2 - hl * pc;
                int p = rr >> 2, j8 = rr & 3;
                const u16* gx = hl ? xl : xh;
                const uint4* src = (const uint4*)(gx +
                    ((size_t)(n * Hp + y0 + r + ky) * Wp + x0 + p) * IC + (kc << 5)) + j8;
                CPA16(sbase + 61440u + (uint32_t)((r * 2 + hl) * (PX + 2) + p) * 80 + j8 * 16, src);
            }
            CP_COMMIT();
            CP_WAIT0();
            __syncthreads();
            for (int kx = 0; kx < 3; kx++)
                #pragma unroll
                for (int ks = 0; ks < 2; ks++) {
                    uint32_t Ah[2][4], Al[2][4];
                    #pragma unroll
                    for (int mt = 0; mt < 2; mt++) {
                        int row = ocg * 32 + mt * 16 + (l & 15);
                        uint32_t a = sbase + (uint32_t)(kx * 128 + row) * 80 + ks * 32 + (l >> 4) * 16;
                        LDSM4(Ah[mt], a);
                        LDSM4(Al[mt], a + 3 * 128 * 80);
                    }
                    #pragma unroll
                    for (int r = 0; r < R; r++) {
                        uint32_t Bh[NT][2], Bl[NT][2];
                        #pragma unroll
                        for (int np = 0; np < NT / 2; np++) {
                            int p = pxg * (NT * 8) + np * 16 + ((l >> 4) << 3) + (l & 7) + kx;
                            uint32_t b = sbase + 61440 + (uint32_t)((r * 2) * (PX + 2) + p) * 80
                                       + ks * 32 + (((l >> 3) & 1) * 16);
                            LDSM4S(Bh[2 * np][0], Bh[2 * np][1],
                                   Bh[2 * np + 1][0], Bh[2 * np + 1][1], b);
                            LDSM4S(Bl[2 * np][0], Bl[2 * np][1],
                                   Bl[2 * np + 1][0], Bl[2 * np + 1][1], b + (PX + 2) * 80);
                        }
                        #pragma unroll
                        for (int mt = 0; mt < 2; mt++)
                            #pragma unroll
                            for (int nt = 0; nt < NT; nt++) {
                                MMA(d[mt][r][nt], Ah[mt], Bh[nt]);
                                MMA(d[mt][r][nt], Ah[mt], Bl[nt]);
                                MMA(d[mt][r][nt], Al[mt], Bh[nt]);
                            }
                    }
                }
        }
    if (mode) {
        size_t plane = (size_t)H * W;
        #pragma unroll
        for (int mt = 0; mt < 2; mt++) {
            int ocr = oc0 + ocg * 32 + mt * 16 + (l >> 2);
            float b0 = bias[ocr], b8 = bias[ocr + 8];
            #pragma unroll
            for (int r = 0; r < R; r++) {
                float* ob = outf + ((size_t)n * OC + ocr) * plane + (size_t)(y0 + r) * W;
                #pragma unroll
                for (int nt = 0; nt < NT; nt++) {
                    int px = x0 + pxg * (NT * 8) + nt * 8 + (l & 3) * 2;
                    *(float2*)(ob + px) = make_float2(
                        fmaxf(d[mt][r][nt][0] + b0, 0.0f), fmaxf(d[mt][r][nt][1] + b0, 0.0f));
                    *(float2*)(ob + 8 * plane + px) = make_float2(
                        fmaxf(d[mt][r][nt][2] + b8, 0.0f), fmaxf(d[mt][r][nt][3] + b8, 0.0f));
                }
            }
        }
    } else {
        #pragma unroll
        for (int mt = 0; mt < 2; mt++) {
            int ocr = oc0 + ocg * 32 + mt * 16 + (l >> 2);
            float b0 = bias[ocr], b8 = bias[ocr + 8];
            #pragma unroll
            for (int r = 0; r < R; r++)
                #pragma unroll
                for (int nt = 0; nt < NT; nt++) {
                    int px = x0 + pxg * (NT * 8) + nt * 8 + (l & 3) * 2;
                    size_t base2 = ((size_t)(n * Hp + y0 + r + 1) * Wp + px + 1) * OC;
                    stsplit(oh, ol, base2 + ocr,          fmaxf(d[mt][r][nt][0] + b0, 0.0f));
                    stsplit(oh, ol, base2 + OC + ocr,     fmaxf(d[mt][r][nt][1] + b0, 0.0f));
                    stsplit(oh, ol, base2 + ocr + 8,      fmaxf(d[mt][r][nt][2] + b8, 0.0f));
                    stsplit(oh, ol, base2 + OC + ocr + 8, fmaxf(d[mt][r][nt][3] + b8, 0.0f));
                }
        }
    }
}

// -------- mma.sync DECONV k3 s2 p1 op1 + relu, cp.async --------
// ky=1 and ky=2 read the same input row; pixel staging skipped at ky==2.
// B fragments loaded pairwise via ldmatrix.x4.
template<int NT>
__global__ __launch_bounds__(256) void deconv_mma_kernel(
    const u16* __restrict__ xh, const u16* __restrict__ xl,
    u16* __restrict__ oh, u16* __restrict__ ol,
    const float* __restrict__ bias,
    int KC, int H, int W, int OC, int IC)
{
    extern __shared__ __align__(16) u16 sm[];
    const int PX = NT * 16;
    int segs = W / PX;
    int y = blockIdx.x / segs, x0 = (blockIdx.x % segs) * PX;
    int oc0 = blockIdx.y << 7, n = blockIdx.z;
    int tid = threadIdx.x, wid = tid >> 5, l = tid & 31;
    int ocg = wid & 3, pxg = wid >> 2;
    int Hp = H + 2, Wp = W + 2;
    uint32_t sbase = smem_u32(sm);
    const u16* gw = (const u16*)g_wscr;
    float d[2][2][2][NT][4];                 // [mt][dy][dx][nt][4]
    #pragma unroll
    for (int mt = 0; mt < 2; mt++)
        #pragma unroll
        for (int a = 0; a < 2; a++)
            #pragma unroll
            for (int b = 0; b < 2; b++)
                #pragma unroll
                for (int nt = 0; nt < NT; nt++)
                    #pragma unroll
                    for (int i = 0; i < 4; i++) d[mt][a][b][nt][i] = 0.0f;

    const int pcd = (PX + 1) * 4;
    for (int kc = 0; kc < KC; kc++)
        for (int ky = 0; ky < 3; ky++) {
            __syncthreads();
            for (int e = tid; e < 3072; e += 256) {
                int j8 = e & 3, oc = (e >> 2) & 127, blk = e >> 9;
                int kx = blk % 3, hl = blk / 3;
                const uint4* src = (const uint4*)(gw +
                    ((((size_t)kc * 9 + ky * 3 + kx) * 2 + hl) * OC + oc0 + oc) * 32) + j8;
                CPA16(sbase + (uint32_t)(blk * 128 + oc) * 80 + j8 * 16, src);
            }
            if (ky != 2) {                   // ky==2 reuses ky==1's pixel row (y+1)
                int ry = y + 1 + (ky == 0);  // padded input row
                for (int e = tid; e < 2 * pcd; e += 256) {
                    int hl = e >= pcd; int r = e - hl * pcd;
                    int p = r >> 2, j8 = r & 3;
                    const u16* gx = hl ? xl : xh;
                    const uint4* src = (const uint4*)(gx +
                        ((size_t)(n * Hp + ry) * Wp + x0 + 1 + p) * IC + (kc << 5)) + j8;
                    CPA16(sbase + 61440u + (uint32_t)(hl * (PX + 1) + p) * 80 + j8 * 16, src);
                }
            }
            CP_COMMIT();
            CP_WAIT0();
            __syncthreads();
            int dy = (ky != 1);
            #pragma unroll
            for (int ks = 0; ks < 2; ks++) {
                uint32_t Bf[2][2][NT][2];    // [hl][shift][nt][2]
                #pragma unroll
                for (int sh = 0; sh < 2; sh++)
                    #pragma unroll
                    for (int np = 0; np < NT / 2; np++) {
                        int p = pxg * (NT * 8) + np * 16 + ((l >> 4) << 3) + (l & 7) + sh;
                        uint32_t b = sbase + 61440 + (uint32_t)p * 80 + ks * 32 + (((l >> 3) & 1) * 16);
                        LDSM4S(Bf[0][sh][2 * np][0], Bf[0][sh][2 * np][1],
                               Bf[0][sh][2 * np + 1][0], Bf[0][sh][2 * np + 1][1], b);
                        LDSM4S(Bf[1][sh][2 * np][0], Bf[1][sh][2 * np][1],
                               Bf[1][sh][2 * np + 1][0], Bf[1][sh][2 * np + 1][1],
                               b + (PX + 1) * 80);
                    }
                for (int kx = 0; kx < 3; kx++) {
                    int sh = (kx == 0), dxp = (kx != 1);
                    uint32_t Ah[2][4], Al[2][4];
                    #pragma unroll
                    for (int mt = 0; mt < 2; mt++) {
                        int row = ocg * 32 + mt * 16 + (l & 15);
                        uint32_t a = sbase + (uint32_t)(kx * 128 + row) * 80 + ks * 32 + (l >> 4) * 16;
                        LDSM4(Ah[mt], a);
                        LDSM4(Al[mt], a + 3 * 128 * 80);
                    }
                    #pragma unroll
                    for (int mt = 0; mt < 2; mt++)
                        #pragma unroll
                        for (int nt = 0; nt < NT; nt++) {
                            MMA(d[mt][dy][dxp][nt], Ah[mt], Bf[0][sh][nt]);
                            MMA(d[mt][dy][dxp][nt], Ah[mt], Bf[1][sh][nt]);
                            MMA(d[mt][dy][dxp][nt], Al[mt], Bf[0][sh][nt]);
                        }
                }
            }
        }
    int OHp = 2 * H + 2, OWp = 2 * W + 2;
    #pragma unroll
    for (int mt = 0; mt < 2; mt++) {
        int ocr = oc0 + ocg * 32 + mt * 16 + (l >> 2);
        float b0 = bias[ocr], b8 = bias[ocr + 8];
        #pragma unroll
        for (int dy2 = 0; dy2 < 2; dy2++)
            #pragma unroll
            for (int dxp = 0; dxp < 2; dxp++)
                #pragma unroll
                for (int nt = 0; nt < NT; nt++) {
                    int p0 = x0 + pxg * (NT * 8) + nt * 8 + 2 * (l & 3);
                    size_t base2 = ((size_t)(n * OHp + 2 * y + dy2 + 1) * OWp + 2 * p0 + dxp + 1) * OC;
                    stsplit(oh, ol, base2 + ocr,              fmaxf(d[mt][dy2][dxp][nt][0] + b0, 0.0f));
                    stsplit(oh, ol, base2 + 2 * OC + ocr,     fmaxf(d[mt][dy2][dxp][nt][1] + b0, 0.0f));
                    stsplit(oh, ol, base2 + ocr + 8,          fmaxf(d[mt][dy2][dxp][nt][2] + b8, 0.0f));
                    stsplit(oh, ol, base2 + 2 * OC + ocr + 8, fmaxf(d[mt][dy2][dxp][nt][3] + b8, 0.0f));
                }
    }
}

// -------- host --------
static void conv_mma(const float* w, const float* b, const u16* xh, const u16* xl,
                     u16* oh, u16* ol, float* outf, int IC, int OC, int H, int W, int mode)
{
    wprep_kernel<<<128, 256>>>(w, OC, IC, 0);
    if (mode == 0) ring_kernel<<<256, 256>>>(oh, ol, OC, H, W);
    if (W >= 128) {
        dim3 grid((W / 128) * (H / 2), OC / 128, 8);
        conv_mma_kernel<8, 2><<<grid, 256, 61440 + 2 * 2 * 130 * 80>>>(
            xh, xl, b, outf, oh, ol, IC / 32, H, W, OC, IC, mode);
    } else {
        dim3 grid((W / 64) * (H / 2), OC / 128, 8);
        conv_mma_kernel<4, 2><<<grid, 256, 61440 + 2 * 2 * 66 * 80>>>(
            xh, xl, b, outf, oh, ol, IC / 32, H, W, OC, IC, mode);
    }
}

static void deconv_mma(const float* w, const float* b, const u16* xh, const u16* xl,
                       u16* oh, u16* ol, int IC, int OC, int H, int W)
{
    wprep_kernel<<<128, 256>>>(w, OC, IC, 1);
    ring_kernel<<<256, 256>>>(oh, ol, OC, 2 * H, 2 * W);
    if (W >= 64) {
        dim3 grid((W / 64) * H, OC / 128, 8);
        deconv_mma_kernel<4><<<grid, 256, 61440 + 2 * 65 * 80>>>(
            xh, xl, oh, ol, b, IC / 32, H, W, OC, IC);
    } else {
        dim3 grid((W / 32) * H, OC / 128, 8);
        deconv_mma_kernel<2><<<grid, 256, 61440 + 2 * 33 * 80>>>(
            xh, xl, oh, ol, b, IC / 32, H, W, OC, IC);
    }
}

extern "C" void kernel_launch(void* const* d_in, const int* in_sizes, int n_in,
                              void* d_out, int out_size)
{
    const float* x   = (const float*)d_in[0];
    const float* We0 = (const float*)d_in[1];
    const float* be0 = (const float*)d_in[2];
    const float* We1 = (const float*)d_in[3];
    const float* be1 = (const float*)d_in[4];
    const float* Wi  = (const float*)d_in[5];
    const float* bi  = (const float*)d_in[6];
    const float* Wd1 = (const float*)d_in[7];
    const float* bd1 = (const float*)d_in[8];
    const float* Wc1 = (const float*)d_in[9];
    const float* bc1 = (const float*)d_in[10];
    const float* Wd2 = (const float*)d_in[11];
    const float* bd2 = (const float*)d_in[12];
    const float* Wc2 = (const float*)d_in[13];
    const float* bc2_ = (const float*)d_in[14];
    const float* Wd3 = (const float*)d_in[15];
    const float* bd3 = (const float*)d_in[16];
    const float* Wc3 = (const float*)d_in[17];
    const float* bc3 = (const float*)d_in[18];
    const float* Wo  = (const float*)d_in[19];
    const float* bo  = (const float*)d_in[20];
    float* out = (float*)d_out;

    static int once = 0;
    if (!once) {
        cudaFuncSetAttribute(conv_mma_kernel<8, 2>, cudaFuncAttributeMaxDynamicSharedMemorySize, 104000);
        cudaFuncSetAttribute(conv_mma_kernel<4, 2>, cudaFuncAttributeMaxDynamicSharedMemorySize, 104000);
        cudaFuncSetAttribute(deconv_mma_kernel<4>, cudaFuncAttributeMaxDynamicSharedMemorySize, 104000);
        cudaFuncSetAttribute(deconv_mma_kernel<2>, cudaFuncAttributeMaxDynamicSharedMemorySize, 104000);
        once = 1;
    }

    float *h3buf, *routed;
    u16 *pAh, *pAl, *pBh, *pBl;
    cudaGetSymbolAddress((void**)&h3buf, g_bufA);
    cudaGetSymbolAddress((void**)&routed, g_routed);
    cudaGetSymbolAddress((void**)&pAh, g_pAh);
    cudaGetSymbolAddress((void**)&pAl, g_pAl);
    cudaGetSymbolAddress((void**)&pBh, g_pBh);
    cudaGetSymbolAddress((void**)&pBl, g_pBl);

    encoder_kernel<<<160, 256>>>(x, We0, be0, We1, be1);
    entropy_kernel<<<2048, 256>>>(x);
    median_kernel<<<1, 1024>>>();
    int write_aux = (out_size >= OUT_FULL) ? 1 : 0;
    route_kernel<<<128, 256>>>(out, write_aux);

    ring_kernel<<<256, 256>>>(pAh, pAl, 256, 32, 32);
    dim3 gWi(4, 4, 8);
    convWi_kernel<<<gWi, 256>>>(routed, Wi, bi, pAh, pAl);
    deconv_mma(Wd1, bd1, pAh, pAl, pBh, pBl, 256, 256, 32, 32);
    conv_mma(Wc1, bc1, pBh, pBl, pAh, pAl, nullptr, 256, 256, 64, 64, 0);
    deconv_mma(Wd2, bd2, pAh, pAl, pBh, pBl, 256, 128, 64, 64);
    conv_mma(Wc2, bc2_, pBh, pBl, pAh, pAl, nullptr, 128, 128, 128, 128, 0);
    deconv_mma(Wd3, bd3, pAh, pAl, pBh, pBl, 128, 128, 128, 128);
    conv_mma(Wc3, bc3, pBh, pBl, nullptr, nullptr, h3buf, 128, 128, 256, 256, 1);
    convWo_kernel<<<256, 256>>>(h3buf, Wo, bo, out);
}

// round 15
// speedup vs baseline: 1.8800x; 1.0040x over previous
#include <cuda_runtime.h>
#include <cuda_bf16.h>
#include <math.h>
#include <stdint.h>

typedef unsigned long long ull;
typedef unsigned short u16;

__device__ __forceinline__ ull pk2(float lo, float hi) {
    ull r; asm("mov.b64 %0, {%1, %2};" : "=l"(r) : "f"(lo), "f"(hi)); return r;
}
__device__ __forceinline__ ull bc2(float v) {
    ull r; asm("mov.b64 %0, {%1, %1};" : "=l"(r) : "f"(v)); return r;
}
__device__ __forceinline__ void fma2(ull& d, ull a, ull b) {
    asm("fma.rn.f32x2 %0, %1, %2, %0;" : "+l"(d) : "l"(a), "l"(b));
}
__device__ __forceinline__ void up2(float& lo, float& hi, ull v) {
    asm("mov.b64 {%0, %1}, %2;" : "=f"(lo), "=f"(hi) : "l"(v));
}
__device__ __forceinline__ uint32_t smem_u32(const void* p) {
    uint32_t a;
    asm("{ .reg .u64 t; cvta.to.shared.u64 t, %1; cvt.u32.u64 %0, t; }" : "=r"(a) : "l"(p));
    return a;
}
__device__ __forceinline__ void stsplit(u16* __restrict__ oh, u16* __restrict__ ol,
                                        size_t o, float v)
{
    __nv_bfloat16 h = __float2bfloat16(v);
    oh[o] = __bfloat16_as_ushort(h);
    ol[o] = __bfloat16_as_ushort(__float2bfloat16(v - __bfloat162float(h)));
}
#define CPA16(dst, src) asm volatile( \
    "cp.async.ca.shared.global [%0], [%1], 16;" :: "r"(dst), "l"(src))
#define CP_COMMIT() asm volatile("cp.async.commit_group;" ::: "memory")
#define CP_WAIT0() asm volatile("cp.async.wait_group 0;" ::: "memory")
#define LDSM4(R, a) asm volatile( \
    "ldmatrix.sync.aligned.m8n8.x4.shared.b16 {%0,%1,%2,%3},[%4];" \
    : "=r"((R)[0]), "=r"((R)[1]), "=r"((R)[2]), "=r"((R)[3]) : "r"(a))
#define LDSM4S(r0, r1, r2, r3, a) asm volatile( \
    "ldmatrix.sync.aligned.m8n8.x4.shared.b16 {%0,%1,%2,%3},[%4];" \
    : "=r"(r0), "=r"(r1), "=r"(r2), "=r"(r3) : "r"(a))
#define MMA(D, A, B) asm volatile( \
    "mma.sync.aligned.m16n8k16.row.col.f32.bf16.bf16.f32 " \
    "{%0,%1,%2,%3},{%4,%5,%6,%7},{%8,%9},{%0,%1,%2,%3};" \
    : "+f"((D)[0]), "+f"((D)[1]), "+f"((D)[2]), "+f"((D)[3]) \
    : "r"((A)[0]), "r"((A)[1]), "r"((A)[2]), "r"((A)[3]), "r"((B)[0]), "r"((B)[1]))

// -------- scratch globals --------
__device__ float g_bufA[67200000];   // h3 fp32 NCHW
__device__ u16 g_pAh[70000000];      // ping NHWC bf16 hi (padded)
__device__ u16 g_pAl[70000000];
__device__ u16 g_pBh[70000000];      // pong
__device__ u16 g_pBl[70000000];
__device__ uint4 g_wscr[150000];     // [kc32][tap][hl][oc][32] bf16
__device__ float g_latf[32768];
__device__ float g_latc[8192];
__device__ float g_ent[2048];
__device__ float g_routed[32768];
__device__ float g_thr;

#define OFF_ROUTED 1572864
#define OFF_GRAIN  1605632
#define OFF_ENT    1607680
#define OUT_FULL   1609728

// -------- encoder --------
__global__ void encoder_kernel(const float* __restrict__ x,
                               const float* __restrict__ We0, const float* __restrict__ be0,
                               const float* __restrict__ We1, const float* __restrict__ be1)
{
    int idx = blockIdx.x * blockDim.x + threadIdx.x;
    if (idx < 32768) {
        int n = idx >> 12, c = (idx >> 10) & 3, oy = (idx >> 5) & 31, ox = idx & 31;
        float acc = be0[c];
        for (int ic = 0; ic < 3; ic++)
            for (int ky = 0; ky < 3; ky++) {
                int iy = oy * 8 - 1 + ky;
                if ((unsigned)iy >= 256u) continue;
                for (int kx = 0; kx < 3; kx++) {
                    int ix = ox * 8 - 1 + kx;
                    if ((unsigned)ix >= 256u) continue;
                    acc += x[((n * 3 + ic) * 256 + iy) * 256 + ix] *
                           We0[((c * 3 + ic) * 3 + ky) * 3 + kx];
                }
            }
        g_latf[idx] = acc;
    } else if (idx < 40960) {
        int i2 = idx - 32768;
        int n = i2 >> 10, c = (i2 >> 8) & 3, oy = (i2 >> 4) & 15, ox = i2 & 15;
        float acc = be1[c];
        for (int ic = 0; ic < 3; ic++)
            for (int ky = 0; ky < 3; ky++) {
                int iy = oy * 16 - 1 + ky;
                if ((unsigned)iy >= 256u) continue;
                for (int kx = 0; kx < 3; kx++) {
                    int ix = ox * 16 - 1 + kx;
                    if ((unsigned)ix >= 256u) continue;
                    acc += x[((n * 3 + ic) * 256 + iy) * 256 + ix] *
                           We1[((c * 3 + ic) * 3 + ky) * 3 + kx];
                }
            }
        g_latc[i2] = acc;
    }
}

// -------- entropy / median / route --------
__global__ void entropy_kernel(const float* __restrict__ x)
{
    __shared__ float g[256];
    __shared__ float red[256];
    int bid = blockIdx.x;
    int b = bid >> 8, hp = (bid >> 4) & 15, wp = bid & 15;
    int tid = threadIdx.x;
    int gy = hp * 16 + (tid >> 4), gx = wp * 16 + (tid & 15);
    const float* xb = x + (size_t)b * 3 * 65536;
    g[tid] = 0.299f * xb[gy * 256 + gx] + 0.587f * xb[65536 + gy * 256 + gx]
           + 0.114f * xb[131072 + gy * 256 + gx];
    __syncthreads();
    for (int k = 2; k <= 256; k <<= 1)
        for (int j = k >> 1; j > 0; j >>= 1) {
            int ixj = tid ^ j;
            if (ixj > tid) {
                float a = g[tid], c2 = g[ixj];
                bool up = (tid & k) == 0;
                if ((a > c2) == up) { g[tid] = c2; g[ixj] = a; }
            }
            __syncthreads();
        }
    float vb = tid * (1.0f / 255.0f);
    float loV = vb - 0.0945f, hiV = vb + 0.0945f;
    int lo = 0, hi = 256;
    while (lo < hi) { int m = (lo + hi) >> 1; if (g[m] < loV) lo = m + 1; else hi = m; }
    int s0 = lo;
    lo = s0; hi = 256;
    while (lo < hi) { int m = (lo + hi) >> 1; if (g[m] <= hiV) lo = m + 1; else hi = m; }
    int s1 = lo;
    float S = 0.0f;
    for (int i = s0; i < s1; i++) {
        float d = (g[i] - vb) * 100.0f;
        S += expf(-0.5f * d * d);
    }
    red[tid] = S;
    __syncthreads();
    for (int st = 128; st > 0; st >>= 1) { if (tid < st) red[tid] += red[tid + st]; __syncthreads(); }
    float T = red[0];
    __syncthreads();
    float p = fmaxf(S / T, 1e-10f);
    red[tid] = p * log2f(p);
    __syncthreads();
    for (int st = 128; st > 0; st >>= 1) { if (tid < st) red[tid] += red[tid + st]; __syncthreads(); }
    if (tid == 0) g_ent[bid] = -red[0];
}

__global__ void median_kernel()
{
    __shared__ float s[2048];
    int tid = threadIdx.x;
    s[tid] = g_ent[tid]; s[tid + 1024] = g_ent[tid + 1024];
    __syncthreads();
    for (int k = 2; k <= 2048; k <<= 1)
        for (int j = k >> 1; j > 0; j >>= 1) {
            for (int base = 0; base < 2048; base += 1024) {
                int i = base + tid, ixj = i ^ j;
                if (ixj > i) {
                    float a = s[i], c2 = s[ixj];
                    bool up = (i & k) == 0;
                    if ((a > c2) == up) { s[i] = c2; s[ixj] = a; }
                }
            }
            __syncthreads();
        }
    if (tid == 0) g_thr = 0.5f * (s[1023] + s[1024]);
}

__global__ void route_kernel(float* __restrict__ out, int write_aux)
{
    int i = blockIdx.x * blockDim.x + threadIdx.x;
    if (i >= 32768) return;
    float thr = g_thr;
    int n = i >> 12, c = (i >> 10) & 3, y = (i >> 5) & 31, xx = i & 31;
    int hp = y >> 1, wp = xx >> 1;
    float e = g_ent[n * 256 + hp * 16 + wp];
    float v = (e > thr) ? g_latf[i] : g_latc[((n * 4 + c) * 16 + hp) * 16 + wp];
    g_routed[i] = v;
    if (write_aux) {
        out[OFF_ROUTED + i] = v;
        if (i < 2048) {
            float ev = g_ent[i];
            out[OFF_GRAIN + i] = (ev > thr) ? 1.0f : 0.0f;
            out[OFF_ENT + i] = ev;
        }
    }
}

// -------- scalar conv Wi: 4->256 @32x32, no relu, OUT = padded NHWC bf16 hi/lo --------
__global__ __launch_bounds__(256, 2) void convWi_kernel(
    const float* __restrict__ in, const float* __restrict__ w,
    const float* __restrict__ bias, u16* __restrict__ oh, u16* __restrict__ ol)
{
    const int C_in = 4, H = 32, W = 32;
    __shared__ __align__(16) float s_in[4][18][20];
    __shared__ ull s_w2[4][9][64];
    int tiles_x = 2;
    int ty = blockIdx.x / tiles_x, tx = blockIdx.x - ty * tiles_x;
    int oc0 = blockIdx.y << 6, n = blockIdx.z;
    int y0 = ty << 4, x0 = tx << 4;
    int tid = threadIdx.x;
    int ocg = tid >> 4, pxg = tid & 15;
    int pr4 = (pxg >> 2) << 2, pc4 = (pxg & 3) << 2;
    ull acc[4][4][2];
    #pragma unroll
    for (int o = 0; o < 4; o++)
        #pragma unroll
        for (int r = 0; r < 4; r++) { acc[o][r][0] = 0; acc[o][r][1] = 0; }
    const float* in_n = in + (size_t)n * C_in * H * W;
    {
        __syncthreads();
        for (int e = tid; e < 4 * 324; e += 256) {
            int ic = e / 324, rem = e - ic * 324;
            int r = rem / 18, cc = rem - r * 18;
            int gy = y0 - 1 + r, gx = x0 - 1 + cc;
            float v = 0.0f;
            if ((unsigned)gy < (unsigned)H && (unsigned)gx < (unsigned)W)
                v = in_n[((size_t)ic * H + gy) * W + gx];
            s_in[ic][r][cc] = v;
        }
        for (int e = tid; e < 4 * 576; e += 256) {
            int ic = e / 576, rem = e - ic * 576;
            int k = rem >> 6, oc = rem & 63;
            s_w2[ic][k][oc] = bc2(w[((size_t)(oc0 + oc) * C_in + ic) * 9 + k]);
        }
        __syncthreads();
        #pragma unroll 1
        for (int ic = 0; ic < 4; ic++)
            #pragma unroll
            for (int ky = 0; ky < 3; ky++) {
                ull w2[3][4];
                #pragma unroll
                for (int kx = 0; kx < 3; kx++)
                    #pragma unroll
                    for (int o = 0; o < 4; o++) w2[kx][o] = s_w2[ic][ky * 3 + kx][(ocg << 2) + o];
                #pragma unroll
                for (int r = 0; r < 4; r++) {
                    const float* rp = &s_in[ic][pr4 + r + ky][pc4];
                    float4 v4 = *(const float4*)rp;
                    float2 v2 = *(const float2*)(rp + 4);
                    ull P0 = pk2(v4.x, v4.y), P1 = pk2(v4.y, v4.z), P2 = pk2(v4.z, v4.w);
                    ull P3 = pk2(v4.w, v2.x), P4 = pk2(v2.x, v2.y);
                    #pragma unroll
                    for (int o = 0; o < 4; o++) {
                        fma2(acc[o][r][0], w2[0][o], P0);
                        fma2(acc[o][r][1], w2[0][o], P2);
                        fma2(acc[o][r][0], w2[1][o], P1);
                        fma2(acc[o][r][1], w2[1][o], P3);
                        fma2(acc[o][r][0], w2[2][o], P2);
                        fma2(acc[o][r][1], w2[2][o], P4);
                    }
                }
            }
    }
    float bv[4];
    #pragma unroll
    for (int o = 0; o < 4; o++) bv[o] = bias[oc0 + (ocg << 2) + o];
    #pragma unroll
    for (int r = 0; r < 4; r++) {
        float vv[4][4];
        #pragma unroll
        for (int o = 0; o < 4; o++) {
            up2(vv[o][0], vv[o][1], acc[o][r][0]);
            up2(vv[o][2], vv[o][3], acc[o][r][1]);
            #pragma unroll
            for (int c = 0; c < 4; c++) vv[o][c] += bv[o];
        }
        int gy = y0 + pr4 + r + 1;
        #pragma unroll
        for (int c = 0; c < 4; c++) {
            u16 hv[4], lv[4];
            #pragma unroll
            for (int o = 0; o < 4; o++) {
                __nv_bfloat16 h = __float2bfloat16(vv[o][c]);
                hv[o] = __bfloat16_as_ushort(h);
                lv[o] = __bfloat16_as_ushort(__float2bfloat16(vv[o][c] - __bfloat162float(h)));
            }
            size_t off = ((size_t)(n * 34 + gy) * 34 + x0 + pc4 + c + 1) * 256 + oc0 + (ocg << 2);
            *(uint2*)&oh[off] = *(uint2*)hv;
            *(uint2*)&ol[off] = *(uint2*)lv;
        }
    }
}

// -------- Wo conv: 128->3, tanh (reads fp32 NCHW) --------
__global__ __launch_bounds__(256) void convWo_kernel(
    const float* __restrict__ in, const float* __restrict__ w,
    const float* __restrict__ bias, float* __restrict__ out)
{
    __shared__ float s_w[3456];
    __shared__ __align__(16) float s_in[2][10][260];
    int n = blockIdx.x >> 5;
    int y0 = (blockIdx.x & 31) << 3;
    int tid = threadIdx.x;
    int rowg = tid >> 6;
    int c4 = (tid & 63) << 2;
    for (int e = tid; e < 3456; e += 256) s_w[e] = w[e];
    ull acc[3][2][2];
    #pragma unroll
    for (int ch = 0; ch < 3; ch++)
        #pragma unroll
        for (int r = 0; r < 2; r++) { acc[ch][r][0] = 0; acc[ch][r][1] = 0; }
    const float* in_n = in + (size_t)n * 128 * 65536;
    for (int ic0 = 0; ic0 < 128; ic0 += 2) {
        __syncthreads();
        for (int e = tid; e < 2 * 2580; e += 256) {
            int ic = e / 2580, rem = e - ic * 2580;
            int rr = rem / 258, cc = rem - rr * 258;
            int gy = y0 - 1 + rr, gx = cc - 1;
            float v = 0.0f;
            if ((unsigned)gy < 256u && (unsigned)gx < 256u)
                v = in_n[(size_t)(ic0 + ic) * 65536 + gy * 256 + gx];
            s_in[ic][rr][cc] = v;
        }
        __syncthreads();
        #pragma unroll
        for (int ic = 0; ic < 2; ic++)
            #pragma unroll
            for (int ky = 0; ky < 3; ky++) {
                ull P[2][5];
                #pragma unroll
                for (int r = 0; r < 2; r++) {
                    const float* rp = &s_in[ic][(rowg << 1) + r + ky][c4];
                    float4 v4 = *(const float4*)rp;
                    float2 v2 = *(const float2*)(rp + 4);
                    P[r][0] = pk2(v4.x, v4.y); P[r][1] = pk2(v4.y, v4.z);
                    P[r][2] = pk2(v4.z, v4.w); P[r][3] = pk2(v4.w, v2.x);
                    P[r][4] = pk2(v2.x, v2.y);
                }
                #pragma unroll
                for (int kx = 0; kx < 3; kx++)
                    #pragma unroll
                    for (int ch = 0; ch < 3; ch++) {
                        ull wb = bc2(s_w[ch * 1152 + (ic0 + ic) * 9 + ky * 3 + kx]);
                        #pragma unroll
                        for (int r = 0; r < 2; r++) {
                            fma2(acc[ch][r][0], wb, P[r][kx]);
                            fma2(acc[ch][r][1], wb, P[r][kx + 2]);
                        }
                    }
            }
    }
    #pragma unroll
    for (int ch = 0; ch < 3; ch++) {
        float bv = bias[ch];
        #pragma unroll
        for (int r = 0; r < 2; r++) {
            int y = y0 + (rowg << 1) + r;
            float f0, f1, f2, f3;
            up2(f0, f1, acc[ch][r][0]); up2(f2, f3, acc[ch][r][1]);
            *(float4*)&out[((size_t)(n * 3 + ch) << 16) + y * 256 + c4] =
                make_float4(tanhf(f0 + bv), tanhf(f1 + bv), tanhf(f2 + bv), tanhf(f3 + bv));
        }
    }
}

// -------- MMA weight prep --------
__global__ void wprep_kernel(const float* __restrict__ w, int OC, int IC, int trans)
{
    int KC = IC >> 5;
    int tot = KC * 9 * OC * 32;
    u16* dst = (u16*)g_wscr;
    for (int idx = blockIdx.x * blockDim.x + threadIdx.x; idx < tot; idx += gridDim.x * blockDim.x) {
        int j = idx & 31;
        int t = idx >> 5;
        int oc = t % OC; t /= OC;
        int tap = t % 9;
        int kc = t / 9;
        float v = trans ? w[((size_t)(kc * 32 + j) * OC + oc) * 9 + tap]
                        : w[((size_t)oc * IC + kc * 32 + j) * 9 + tap];
        __nv_bfloat16 h = __float2bfloat16(v);
        __nv_bfloat16 l = __float2bfloat16(v - __bfloat162float(h));
        size_t b = ((((size_t)kc * 9 + tap) * 2 + 0) * OC + oc) * 32 + j;
        size_t b2 = ((((size_t)kc * 9 + tap) * 2 + 1) * OC + oc) * 32 + j;
        dst[b] = __bfloat16_as_ushort(h);
        dst[b2] = __bfloat16_as_ushort(l);
    }
}

// -------- pad-ring zero --------
__global__ void ring_kernel(u16* __restrict__ oh, u16* __restrict__ ol, int C, int H, int W)
{
    int Hp = H + 2, Wp = W + 2, IC8 = C >> 3;
    int per = (2 * Wp + 2 * H) * IC8;
    int tot = 8 * per;
    uint4 z = make_uint4(0, 0, 0, 0);
    uint4* h4 = (uint4*)oh;
    uint4* l4 = (uint4*)ol;
    for (int idx = blockIdx.x * blockDim.x + threadIdx.x; idx < tot; idx += gridDim.x * blockDim.x) {
        int n = idx / per, r = idx % per;
        int pix = r / IC8, c = r % IC8;
        int y, x;
        if (pix < Wp) { y = 0; x = pix; }
        else if (pix < 2 * Wp) { y = Hp - 1; x = pix - Wp; }
        else { int q = pix - 2 * Wp; y = 1 + (q >> 1); x = (q & 1) ? Wp - 1 : 0; }
        size_t o = ((size_t)(n * Hp + y) * Wp + x) * IC8 + c;
        h4[o] = z; l4[o] = z;
    }
}

// -------- mma.sync conv 3x3 s1 p1 (3-pass hi/lo), cp.async, R rows/block --------
// B fragments loaded pairwise via ldmatrix.x4 (lanes 16-31 -> nt+1).
template<int NT, int R>
__global__ __launch_bounds__(256) void conv_mma_kernel(
    const u16* __restrict__ xh, const u16* __restrict__ xl,
    const float* __restrict__ bias,
    float* __restrict__ outf, u16* __restrict__ oh, u16* __restrict__ ol,
    int KC, int H, int W, int OC, int IC, int mode)
{
    extern __shared__ __align__(16) u16 sm[];
    const int PX = NT * 16;
    int segs = W / PX;
    int yb = blockIdx.x / segs, x0 = (blockIdx.x % segs) * PX;
    int y0 = yb * R;
    int oc0 = blockIdx.y << 7, n = blockIdx.z;
    int tid = threadIdx.x, wid = tid >> 5, l = tid & 31;
    int ocg = wid & 3, pxg = wid >> 2;
    int Hp = H + 2, Wp = W + 2;
    uint32_t sbase = smem_u32(sm);
    const u16* gw = (const u16*)g_wscr;
    float d[2][R][NT][4];
    #pragma unroll
    for (int mt = 0; mt < 2; mt++)
        #pragma unroll
        for (int r = 0; r < R; r++)
            #pragma unroll
            for (int nt = 0; nt < NT; nt++)
                #pragma unroll
                for (int i = 0; i < 4; i++) d[mt][r][nt][i] = 0.0f;

    const int pc = (PX + 2) * 4;
    for (int kc = 0; kc < KC; kc++)
        for (int ky = 0; ky < 3; ky++) {
            __syncthreads();
            for (int e = tid; e < 3072; e += 256) {
                int j8 = e & 3, oc = (e >> 2) & 127, blk = e >> 9;
                int kx = blk % 3, hl = blk / 3;
                const uint4* src = (const uint4*)(gw +
                    ((((size_t)kc * 9 + ky * 3 + kx) * 2 + hl) * OC + oc0 + oc) * 32) + j8;
                CPA16(sbase + (uint32_t)(blk * 128 + oc) * 80 + j8 * 16, src);
            }
            for (int e = tid; e < R * 2 * pc; e += 256) {
                int r = e / (2 * pc);
                int e2 = e - r * 2 * pc;
                int hl = e2 >= pc; int rr = e2 - hl * pc;
                int p = rr >> 2, j8 = rr & 3;
                const u16* gx = hl ? xl : xh;
                const uint4* src = (const uint4*)(gx +
                    ((size_t)(n * Hp + y0 + r + ky) * Wp + x0 + p) * IC + (kc << 5)) + j8;
                CPA16(sbase + 61440u + (uint32_t)((r * 2 + hl) * (PX + 2) + p) * 80 + j8 * 16, src);
            }
            CP_COMMIT();
            CP_WAIT0();
            __syncthreads();
            for (int kx = 0; kx < 3; kx++)
                #pragma unroll
                for (int ks = 0; ks < 2; ks++) {
                    uint32_t Ah[2][4], Al[2][4];
                    #pragma unroll
                    for (int mt = 0; mt < 2; mt++) {
                        int row = ocg * 32 + mt * 16 + (l & 15);
                        uint32_t a = sbase + (uint32_t)(kx * 128 + row) * 80 + ks * 32 + (l >> 4) * 16;
                        LDSM4(Ah[mt], a);
                        LDSM4(Al[mt], a + 3 * 128 * 80);
                    }
                    #pragma unroll
                    for (int r = 0; r < R; r++) {
                        uint32_t Bh[NT][2], Bl[NT][2];
                        #pragma unroll
                        for (int np = 0; np < NT / 2; np++) {
                            int p = pxg * (NT * 8) + np * 16 + ((l >> 4) << 3) + (l & 7) + kx;
                            uint32_t b = sbase + 61440 + (uint32_t)((r * 2) * (PX + 2) + p) * 80
                                       + ks * 32 + (((l >> 3) & 1) * 16);
                            LDSM4S(Bh[2 * np][0], Bh[2 * np][1],
                                   Bh[2 * np + 1][0], Bh[2 * np + 1][1], b);
                            LDSM4S(Bl[2 * np][0], Bl[2 * np][1],
                                   Bl[2 * np + 1][0], Bl[2 * np + 1][1], b + (PX + 2) * 80);
                        }
                        #pragma unroll
                        for (int mt = 0; mt < 2; mt++)
                            #pragma unroll
                            for (int nt = 0; nt < NT; nt++) {
                                MMA(d[mt][r][nt], Ah[mt], Bh[nt]);
                                MMA(d[mt][r][nt], Ah[mt], Bl[nt]);
                                MMA(d[mt][r][nt], Al[mt], Bh[nt]);
                            }
                    }
                }
        }
    if (mode) {
        size_t plane = (size_t)H * W;
        #pragma unroll
        for (int mt = 0; mt < 2; mt++) {
            int ocr = oc0 + ocg * 32 + mt * 16 + (l >> 2);
            float b0 = bias[ocr], b8 = bias[ocr + 8];
            #pragma unroll
            for (int r = 0; r < R; r++) {
                float* ob = outf + ((size_t)n * OC + ocr) * plane + (size_t)(y0 + r) * W;
                #pragma unroll
                for (int nt = 0; nt < NT; nt++) {
                    int px = x0 + pxg * (NT * 8) + nt * 8 + (l & 3) * 2;
                    *(float2*)(ob + px) = make_float2(
                        fmaxf(d[mt][r][nt][0] + b0, 0.0f), fmaxf(d[mt][r][nt][1] + b0, 0.0f));
                    *(float2*)(ob + 8 * plane + px) = make_float2(
                        fmaxf(d[mt][r][nt][2] + b8, 0.0f), fmaxf(d[mt][r][nt][3] + b8, 0.0f));
                }
            }
        }
    } else {
        #pragma unroll
        for (int mt = 0; mt < 2; mt++) {
            int ocr = oc0 + ocg * 32 + mt * 16 + (l >> 2);
            float b0 = bias[ocr], b8 = bias[ocr + 8];
            #pragma unroll
            for (int r = 0; r < R; r++)
                #pragma unroll
                for (int nt = 0; nt < NT; nt++) {
                    int px = x0 + pxg * (NT * 8) + nt * 8 + (l & 3) * 2;
                    size_t base2 = ((size_t)(n * Hp + y0 + r + 1) * Wp + px + 1) * OC;
                    stsplit(oh, ol, base2 + ocr,          fmaxf(d[mt][r][nt][0] + b0, 0.0f));
                    stsplit(oh, ol, base2 + OC + ocr,     fmaxf(d[mt][r][nt][1] + b0, 0.0f));
                    stsplit(oh, ol, base2 + ocr + 8,      fmaxf(d[mt][r][nt][2] + b8, 0.0f));
                    stsplit(oh, ol, base2 + OC + ocr + 8, fmaxf(d[mt][r][nt][3] + b8, 0.0f));
                }
        }
    }
}

// -------- mma.sync DECONV k3 s2 p1 op1 + relu, cp.async --------
// ky=1 and ky=2 read the same input row; pixel staging skipped at ky==2.
// B fragments loaded pairwise via ldmatrix.x4.
template<int NT>
__global__ __launch_bounds__(256) void deconv_mma_kernel(
    const u16* __restrict__ xh, const u16* __restrict__ xl,
    u16* __restrict__ oh, u16* __restrict__ ol,
    const float* __restrict__ bias,
    int KC, int H, int W, int OC, int IC)
{
    extern __shared__ __align__(16) u16 sm[];
    const int PX = NT * 16;
    int segs = W / PX;
    int y = blockIdx.x / segs, x0 = (blockIdx.x % segs) * PX;
    int oc0 = blockIdx.y << 7, n = blockIdx.z;
    int tid = threadIdx.x, wid = tid >> 5, l = tid & 31;
    int ocg = wid & 3, pxg = wid >> 2;
    int Hp = H + 2, Wp = W + 2;
    uint32_t sbase = smem_u32(sm);
    const u16* gw = (const u16*)g_wscr;
    float d[2][2][2][NT][4];                 // [mt][dy][dx][nt][4]
    #pragma unroll
    for (int mt = 0; mt < 2; mt++)
        #pragma unroll
        for (int a = 0; a < 2; a++)
            #pragma unroll
            for (int b = 0; b < 2; b++)
                #pragma unroll
                for (int nt = 0; nt < NT; nt++)
                    #pragma unroll
                    for (int i = 0; i < 4; i++) d[mt][a][b][nt][i] = 0.0f;

    const int pcd = (PX + 1) * 4;
    for (int kc = 0; kc < KC; kc++)
        for (int ky = 0; ky < 3; ky++) {
            __syncthreads();
            for (int e = tid; e < 3072; e += 256) {
                int j8 = e & 3, oc = (e >> 2) & 127, blk = e >> 9;
                int kx = blk % 3, hl = blk / 3;
                const uint4* src = (const uint4*)(gw +
                    ((((size_t)kc * 9 + ky * 3 + kx) * 2 + hl) * OC + oc0 + oc) * 32) + j8;
                CPA16(sbase + (uint32_t)(blk * 128 + oc) * 80 + j8 * 16, src);
            }
            if (ky != 2) {                   // ky==2 reuses ky==1's pixel row (y+1)
                int ry = y + 1 + (ky == 0);  // padded input row
                for (int e = tid; e < 2 * pcd; e += 256) {
                    int hl = e >= pcd; int r = e - hl * pcd;
                    int p = r >> 2, j8 = r & 3;
                    const u16* gx = hl ? xl : xh;
                    const uint4* src = (const uint4*)(gx +
                        ((size_t)(n * Hp + ry) * Wp + x0 + 1 + p) * IC + (kc << 5)) + j8;
                    CPA16(sbase + 61440u + (uint32_t)(hl * (PX + 1) + p) * 80 + j8 * 16, src);
                }
            }
            CP_COMMIT();
            CP_WAIT0();
            __syncthreads();
            int dy = (ky != 1);
            #pragma unroll
            for (int ks = 0; ks < 2; ks++) {
                uint32_t Bf[2][2][NT][2];    // [hl][shift][nt][2]
                #pragma unroll
                for (int sh = 0; sh < 2; sh++)
                    #pragma unroll
                    for (int np = 0; np < NT / 2; np++) {
                        int p = pxg * (NT * 8) + np * 16 + ((l >> 4) << 3) + (l & 7) + sh;
                        uint32_t b = sbase + 61440 + (uint32_t)p * 80 + ks * 32 + (((l >> 3) & 1) * 16);
                        LDSM4S(Bf[0][sh][2 * np][0], Bf[0][sh][2 * np][1],
                               Bf[0][sh][2 * np + 1][0], Bf[0][sh][2 * np + 1][1], b);
                        LDSM4S(Bf[1][sh][2 * np][0], Bf[1][sh][2 * np][1],
                               Bf[1][sh][2 * np + 1][0], Bf[1][sh][2 * np + 1][1],
                               b + (PX + 1) * 80);
                    }
                for (int kx = 0; kx < 3; kx++) {
                    int sh = (kx == 0), dxp = (kx != 1);
                    uint32_t Ah[2][4], Al[2][4];
                    #pragma unroll
                    for (int mt = 0; mt < 2; mt++) {
                        int row = ocg * 32 + mt * 16 + (l & 15);
                        uint32_t a = sbase + (uint32_t)(kx * 128 + row) * 80 + ks * 32 + (l >> 4) * 16;
                        LDSM4(Ah[mt], a);
                        LDSM4(Al[mt], a + 3 * 128 * 80);
                    }
                    #pragma unroll
                    for (int mt = 0; mt < 2; mt++)
                        #pragma unroll
                        for (int nt = 0; nt < NT; nt++) {
                            MMA(d[mt][dy][dxp][nt], Ah[mt], Bf[0][sh][nt]);
                            MMA(d[mt][dy][dxp][nt], Ah[mt], Bf[1][sh][nt]);
                            MMA(d[mt][dy][dxp][nt], Al[mt], Bf[0][sh][nt]);
                        }
                }
            }
        }
    int OHp = 2 * H + 2, OWp = 2 * W + 2;
    #pragma unroll
    for (int mt = 0; mt < 2; mt++) {
        int ocr = oc0 + ocg * 32 + mt * 16 + (l >> 2);
        float b0 = bias[ocr], b8 = bias[ocr + 8];
        #pragma unroll
        for (int dy2 = 0; dy2 < 2; dy2++)
            #pragma unroll
            for (int dxp = 0; dxp < 2; dxp++)
                #pragma unroll
                for (int nt = 0; nt < NT; nt++) {
                    int p0 = x0 + pxg * (NT * 8) + nt * 8 + 2 * (l & 3);
                    size_t base2 = ((size_t)(n * OHp + 2 * y + dy2 + 1) * OWp + 2 * p0 + dxp + 1) * OC;
                    stsplit(oh, ol, base2 + ocr,              fmaxf(d[mt][dy2][dxp][nt][0] + b0, 0.0f));
                    stsplit(oh, ol, base2 + 2 * OC + ocr,     fmaxf(d[mt][dy2][dxp][nt][1] + b0, 0.0f));
                    stsplit(oh, ol, base2 + ocr + 8,          fmaxf(d[mt][dy2][dxp][nt][2] + b8, 0.0f));
                    stsplit(oh, ol, base2 + 2 * OC + ocr + 8, fmaxf(d[mt][dy2][dxp][nt][3] + b8, 0.0f));
                }
    }
}

// -------- host --------
static void conv_mma(const float* w, const float* b, const u16* xh, const u16* xl,
                     u16* oh, u16* ol, float* outf, int IC, int OC, int H, int W, int mode)
{
    wprep_kernel<<<128, 256>>>(w, OC, IC, 0);
    if (mode == 0) ring_kernel<<<256, 256>>>(oh, ol, OC, H, W);
    if (W >= 128) {
        dim3 grid((W / 128) * (H / 2), OC / 128, 8);
        conv_mma_kernel<8, 2><<<grid, 256, 61440 + 2 * 2 * 130 * 80>>>(
            xh, xl, b, outf, oh, ol, IC / 32, H, W, OC, IC, mode);
    } else {
        dim3 grid((W / 64) * (H / 4), OC / 128, 8);
        conv_mma_kernel<4, 4><<<grid, 256, 61440 + 4 * 2 * 66 * 80>>>(
            xh, xl, b, outf, oh, ol, IC / 32, H, W, OC, IC, mode);
    }
}

static void deconv_mma(const float* w, const float* b, const u16* xh, const u16* xl,
                       u16* oh, u16* ol, int IC, int OC, int H, int W)
{
    wprep_kernel<<<128, 256>>>(w, OC, IC, 1);
    ring_kernel<<<256, 256>>>(oh, ol, OC, 2 * H, 2 * W);
    if (W >= 64) {
        dim3 grid((W / 64) * H, OC / 128, 8);
        deconv_mma_kernel<4><<<grid, 256, 61440 + 2 * 65 * 80>>>(
            xh, xl, oh, ol, b, IC / 32, H, W, OC, IC);
    } else {
        dim3 grid((W / 32) * H, OC / 128, 8);
        deconv_mma_kernel<2><<<grid, 256, 61440 + 2 * 33 * 80>>>(
            xh, xl, oh, ol, b, IC / 32, H, W, OC, IC);
    }
}

extern "C" void kernel_launch(void* const* d_in, const int* in_sizes, int n_in,
                              void* d_out, int out_size)
{
    const float* x   = (const float*)d_in[0];
    const float* We0 = (const float*)d_in[1];
    const float* be0 = (const float*)d_in[2];
    const float* We1 = (const float*)d_in[3];
    const float* be1 = (const float*)d_in[4];
    const float* Wi  = (const float*)d_in[5];
    const float* bi  = (const float*)d_in[6];
    const float* Wd1 = (const float*)d_in[7];
    const float* bd1 = (const float*)d_in[8];
    const float* Wc1 = (const float*)d_in[9];
    const float* bc1 = (const float*)d_in[10];
    const float* Wd2 = (const float*)d_in[11];
    const float* bd2 = (const float*)d_in[12];
    const float* Wc2 = (const float*)d_in[13];
    const float* bc2_ = (const float*)d_in[14];
    const float* Wd3 = (const float*)d_in[15];
    const float* bd3 = (const float*)d_in[16];
    const float* Wc3 = (const float*)d_in[17];
    const float* bc3 = (const float*)d_in[18];
    const float* Wo  = (const float*)d_in[19];
    const float* bo  = (const float*)d_in[20];
    float* out = (float*)d_out;

    static int once = 0;
    if (!once) {
        cudaFuncSetAttribute(conv_mma_kernel<8, 2>, cudaFuncAttributeMaxDynamicSharedMemorySize, 104000);
        cudaFuncSetAttribute(conv_mma_kernel<4, 4>, cudaFuncAttributeMaxDynamicSharedMemorySize, 104000);
        cudaFuncSetAttribute(deconv_mma_kernel<4>, cudaFuncAttributeMaxDynamicSharedMemorySize, 104000);
        cudaFuncSetAttribute(deconv_mma_kernel<2>, cudaFuncAttributeMaxDynamicSharedMemorySize, 104000);
        once = 1;
    }

    float *h3buf, *routed;
    u16 *pAh, *pAl, *pBh, *pBl;
    cudaGetSymbolAddress((void**)&h3buf, g_bufA);
    cudaGetSymbolAddress((void**)&routed, g_routed);
    cudaGetSymbolAddress((void**)&pAh, g_pAh);
    cudaGetSymbolAddress((void**)&pAl, g_pAl);
    cudaGetSymbolAddress((void**)&pBh, g_pBh);
    cudaGetSymbolAddress((void**)&pBl, g_pBl);

    encoder_kernel<<<160, 256>>>(x, We0, be0, We1, be1);
    entropy_kernel<<<2048, 256>>>(x);
    median_kernel<<<1, 1024>>>();
    int write_aux = (out_size >= OUT_FULL) ? 1 : 0;
    route_kernel<<<128, 256>>>(out, write_aux);

    ring_kernel<<<256, 256>>>(pAh, pAl, 256, 32, 32);
    dim3 gWi(4, 4, 8);
    convWi_kernel<<<gWi, 256>>>(routed, Wi, bi, pAh, pAl);
    deconv_mma(Wd1, bd1, pAh, pAl, pBh, pBl, 256, 256, 32, 32);
    conv_mma(Wc1, bc1, pBh, pBl, pAh, pAl, nullptr, 256, 256, 64, 64, 0);
    deconv_mma(Wd2, bd2, pAh, pAl, pBh, pBl, 256, 128, 64, 64);
    conv_mma(Wc2, bc2_, pBh, pBl, pAh, pAl, nullptr, 128, 128, 128, 128, 0);
    deconv_mma(Wd3, bd3, pAh, pAl, pBh, pBl, 128, 128, 128, 128);
    conv_mma(Wc3, bc3, pBh, pBl, nullptr, nullptr, h3buf, 128, 128, 256, 256, 1);
    convWo_kernel<<<256, 256>>>(h3buf, Wo, bo, out);
}

// round 17
// speedup vs baseline: 1.9718x; 1.0489x over previous
#include <cuda_runtime.h>
#include <cuda_bf16.h>
#include <math.h>
#include <stdint.h>

typedef unsigned long long ull;
typedef unsigned short u16;

__device__ __forceinline__ ull pk2(float lo, float hi) {
    ull r; asm("mov.b64 %0, {%1, %2};" : "=l"(r) : "f"(lo), "f"(hi)); return r;
}
__device__ __forceinline__ ull bc2(float v) {
    ull r; asm("mov.b64 %0, {%1, %1};" : "=l"(r) : "f"(v)); return r;
}
__device__ __forceinline__ void fma2(ull& d, ull a, ull b) {
    asm("fma.rn.f32x2 %0, %1, %2, %0;" : "+l"(d) : "l"(a), "l"(b));
}
__device__ __forceinline__ void up2(float& lo, float& hi, ull v) {
    asm("mov.b64 {%0, %1}, %2;" : "=f"(lo), "=f"(hi) : "l"(v));
}
__device__ __forceinline__ uint32_t smem_u32(const void* p) {
    uint32_t a;
    asm("{ .reg .u64 t; cvta.to.shared.u64 t, %1; cvt.u32.u64 %0, t; }" : "=r"(a) : "l"(p));
    return a;
}
__device__ __forceinline__ void stsplit(u16* __restrict__ oh, u16* __restrict__ ol,
                                        size_t o, float v)
{
    __nv_bfloat16 h = __float2bfloat16(v);
    oh[o] = __bfloat16_as_ushort(h);
    ol[o] = __bfloat16_as_ushort(__float2bfloat16(v - __bfloat162float(h)));
}
#define CPA16(dst, src) asm volatile( \
    "cp.async.ca.shared.global [%0], [%1], 16;" :: "r"(dst), "l"(src))
#define CP_COMMIT() asm volatile("cp.async.commit_group;" ::: "memory")
#define CP_WAIT0() asm volatile("cp.async.wait_group 0;" ::: "memory")
#define LDSM4(R, a) asm volatile( \
    "ldmatrix.sync.aligned.m8n8.x4.shared.b16 {%0,%1,%2,%3},[%4];" \
    : "=r"((R)[0]), "=r"((R)[1]), "=r"((R)[2]), "=r"((R)[3]) : "r"(a))
#define LDSM4S(r0, r1, r2, r3, a) asm volatile( \
    "ldmatrix.sync.aligned.m8n8.x4.shared.b16 {%0,%1,%2,%3},[%4];" \
    : "=r"(r0), "=r"(r1), "=r"(r2), "=r"(r3) : "r"(a))
#define MMA(D, A, B) asm volatile( \
    "mma.sync.aligned.m16n8k16.row.col.f32.bf16.bf16.f32 " \
    "{%0,%1,%2,%3},{%4,%5,%6,%7},{%8,%9},{%0,%1,%2,%3};" \
    : "+f"((D)[0]), "+f"((D)[1]), "+f"((D)[2]), "+f"((D)[3]) \
    : "r"((A)[0]), "r"((A)[1]), "r"((A)[2]), "r"((A)[3]), "r"((B)[0]), "r"((B)[1]))

// -------- scratch globals --------
__device__ float g_bufA[67200000];   // h3 fp32 NCHW
__device__ u16 g_pAh[70000000];      // ping NHWC bf16 hi (padded)
__device__ u16 g_pAl[70000000];
__device__ u16 g_pBh[70000000];      // pong
__device__ u16 g_pBl[70000000];
__device__ uint4 g_wscr[150000];     // [kc32][tap][hl][oc][32] bf16
__device__ float g_latf[32768];
__device__ float g_latc[8192];
__device__ float g_ent[2048];
__device__ float g_routed[32768];
__device__ float g_thr;

#define OFF_ROUTED 1572864
#define OFF_GRAIN  1605632
#define OFF_ENT    1607680
#define OUT_FULL   1609728

// -------- encoder --------
__global__ void encoder_kernel(const float* __restrict__ x,
                               const float* __restrict__ We0, const float* __restrict__ be0,
                               const float* __restrict__ We1, const float* __restrict__ be1)
{
    int idx = blockIdx.x * blockDim.x + threadIdx.x;
    if (idx < 32768) {
        int n = idx >> 12, c = (idx >> 10) & 3, oy = (idx >> 5) & 31, ox = idx & 31;
        float acc = be0[c];
        for (int ic = 0; ic < 3; ic++)
            for (int ky = 0; ky < 3; ky++) {
                int iy = oy * 8 - 1 + ky;
                if ((unsigned)iy >= 256u) continue;
                for (int kx = 0; kx < 3; kx++) {
                    int ix = ox * 8 - 1 + kx;
                    if ((unsigned)ix >= 256u) continue;
                    acc += x[((n * 3 + ic) * 256 + iy) * 256 + ix] *
                           We0[((c * 3 + ic) * 3 + ky) * 3 + kx];
                }
            }
        g_latf[idx] = acc;
    } else if (idx < 40960) {
        int i2 = idx - 32768;
        int n = i2 >> 10, c = (i2 >> 8) & 3, oy = (i2 >> 4) & 15, ox = i2 & 15;
        float acc = be1[c];
        for (int ic = 0; ic < 3; ic++)
            for (int ky = 0; ky < 3; ky++) {
                int iy = oy * 16 - 1 + ky;
                if ((unsigned)iy >= 256u) continue;
                for (int kx = 0; kx < 3; kx++) {
                    int ix = ox * 16 - 1 + kx;
                    if ((unsigned)ix >= 256u) continue;
                    acc += x[((n * 3 + ic) * 256 + iy) * 256 + ix] *
                           We1[((c * 3 + ic) * 3 + ky) * 3 + kx];
                }
            }
        g_latc[i2] = acc;
    }
}

// -------- entropy / median / route --------
__global__ void entropy_kernel(const float* __restrict__ x)
{
    __shared__ float g[256];
    __shared__ float red[256];
    int bid = blockIdx.x;
    int b = bid >> 8, hp = (bid >> 4) & 15, wp = bid & 15;
    int tid = threadIdx.x;
    int gy = hp * 16 + (tid >> 4), gx = wp * 16 + (tid & 15);
    const float* xb = x + (size_t)b * 3 * 65536;
    g[tid] = 0.299f * xb[gy * 256 + gx] + 0.587f * xb[65536 + gy * 256 + gx]
           + 0.114f * xb[131072 + gy * 256 + gx];
    __syncthreads();
    for (int k = 2; k <= 256; k <<= 1)
        for (int j = k >> 1; j > 0; j >>= 1) {
            int ixj = tid ^ j;
            if (ixj > tid) {
                float a = g[tid], c2 = g[ixj];
                bool up = (tid & k) == 0;
                if ((a > c2) == up) { g[tid] = c2; g[ixj] = a; }
            }
            __syncthreads();
        }
    float vb = tid * (1.0f / 255.0f);
    float loV = vb - 0.0945f, hiV = vb + 0.0945f;
    int lo = 0, hi = 256;
    while (lo < hi) { int m = (lo + hi) >> 1; if (g[m] < loV) lo = m + 1; else hi = m; }
    int s0 = lo;
    lo = s0; hi = 256;
    while (lo < hi) { int m = (lo + hi) >> 1; if (g[m] <= hiV) lo = m + 1; else hi = m; }
    int s1 = lo;
    float S = 0.0f;
    for (int i = s0; i < s1; i++) {
        float d = (g[i] - vb) * 100.0f;
        S += expf(-0.5f * d * d);
    }
    red[tid] = S;
    __syncthreads();
    for (int st = 128; st > 0; st >>= 1) { if (tid < st) red[tid] += red[tid + st]; __syncthreads(); }
    float T = red[0];
    __syncthreads();
    float p = fmaxf(S / T, 1e-10f);
    red[tid] = p * log2f(p);
    __syncthreads();
    for (int st = 128; st > 0; st >>= 1) { if (tid < st) red[tid] += red[tid + st]; __syncthreads(); }
    if (tid == 0) g_ent[bid] = -red[0];
}

__global__ void median_kernel()
{
    __shared__ float s[2048];
    int tid = threadIdx.x;
    s[tid] = g_ent[tid]; s[tid + 1024] = g_ent[tid + 1024];
    __syncthreads();
    for (int k = 2; k <= 2048; k <<= 1)
        for (int j = k >> 1; j > 0; j >>= 1) {
            for (int base = 0; base < 2048; base += 1024) {
                int i = base + tid, ixj = i ^ j;
                if (ixj > i) {
                    float a = s[i], c2 = s[ixj];
                    bool up = (i & k) == 0;
                    if ((a > c2) == up) { s[i] = c2; s[ixj] = a; }
                }
            }
            __syncthreads();
        }
    if (tid == 0) g_thr = 0.5f * (s[1023] + s[1024]);
}

__global__ void route_kernel(float* __restrict__ out, int write_aux)
{
    int i = blockIdx.x * blockDim.x + threadIdx.x;
    if (i >= 32768) return;
    float thr = g_thr;
    int n = i >> 12, c = (i >> 10) & 3, y = (i >> 5) & 31, xx = i & 31;
    int hp = y >> 1, wp = xx >> 1;
    float e = g_ent[n * 256 + hp * 16 + wp];
    float v = (e > thr) ? g_latf[i] : g_latc[((n * 4 + c) * 16 + hp) * 16 + wp];
    g_routed[i] = v;
    if (write_aux) {
        out[OFF_ROUTED + i] = v;
        if (i < 2048) {
            float ev = g_ent[i];
            out[OFF_GRAIN + i] = (ev > thr) ? 1.0f : 0.0f;
            out[OFF_ENT + i] = ev;
        }
    }
}

// -------- scalar conv Wi: 4->256 @32x32, no relu, OUT = padded NHWC bf16 hi/lo --------
__global__ __launch_bounds__(256, 2) void convWi_kernel(
    const float* __restrict__ in, const float* __restrict__ w,
    const float* __restrict__ bias, u16* __restrict__ oh, u16* __restrict__ ol)
{
    const int C_in = 4, H = 32, W = 32;
    __shared__ __align__(16) float s_in[4][18][20];
    __shared__ ull s_w2[4][9][64];
    int tiles_x = 2;
    int ty = blockIdx.x / tiles_x, tx = blockIdx.x - ty * tiles_x;
    int oc0 = blockIdx.y << 6, n = blockIdx.z;
    int y0 = ty << 4, x0 = tx << 4;
    int tid = threadIdx.x;
    int ocg = tid >> 4, pxg = tid & 15;
    int pr4 = (pxg >> 2) << 2, pc4 = (pxg & 3) << 2;
    ull acc[4][4][2];
    #pragma unroll
    for (int o = 0; o < 4; o++)
        #pragma unroll
        for (int r = 0; r < 4; r++) { acc[o][r][0] = 0; acc[o][r][1] = 0; }
    const float* in_n = in + (size_t)n * C_in * H * W;
    {
        __syncthreads();
        for (int e = tid; e < 4 * 324; e += 256) {
            int ic = e / 324, rem = e - ic * 324;
            int r = rem / 18, cc = rem - r * 18;
            int gy = y0 - 1 + r, gx = x0 - 1 + cc;
            float v = 0.0f;
            if ((unsigned)gy < (unsigned)H && (unsigned)gx < (unsigned)W)
                v = in_n[((size_t)ic * H + gy) * W + gx];
            s_in[ic][r][cc] = v;
        }
        for (int e = tid; e < 4 * 576; e += 256) {
            int ic = e / 576, rem = e - ic * 576;
            int k = rem >> 6, oc = rem & 63;
            s_w2[ic][k][oc] = bc2(w[((size_t)(oc0 + oc) * C_in + ic) * 9 + k]);
        }
        __syncthreads();
        #pragma unroll 1
        for (int ic = 0; ic < 4; ic++)
            #pragma unroll
            for (int ky = 0; ky < 3; ky++) {
                ull w2[3][4];
                #pragma unroll
                for (int kx = 0; kx < 3; kx++)
                    #pragma unroll
                    for (int o = 0; o < 4; o++) w2[kx][o] = s_w2[ic][ky * 3 + kx][(ocg << 2) + o];
                #pragma unroll
                for (int r = 0; r < 4; r++) {
                    const float* rp = &s_in[ic][pr4 + r + ky][pc4];
                    float4 v4 = *(const float4*)rp;
                    float2 v2 = *(const float2*)(rp + 4);
                    ull P0 = pk2(v4.x, v4.y), P1 = pk2(v4.y, v4.z), P2 = pk2(v4.z, v4.w);
                    ull P3 = pk2(v4.w, v2.x), P4 = pk2(v2.x, v2.y);
                    #pragma unroll
                    for (int o = 0; o < 4; o++) {
                        fma2(acc[o][r][0], w2[0][o], P0);
                        fma2(acc[o][r][1], w2[0][o], P2);
                        fma2(acc[o][r][0], w2[1][o], P1);
                        fma2(acc[o][r][1], w2[1][o], P3);
                        fma2(acc[o][r][0], w2[2][o], P2);
                        fma2(acc[o][r][1], w2[2][o], P4);
                    }
                }
            }
    }
    float bv[4];
    #pragma unroll
    for (int o = 0; o < 4; o++) bv[o] = bias[oc0 + (ocg << 2) + o];
    #pragma unroll
    for (int r = 0; r < 4; r++) {
        float vv[4][4];
        #pragma unroll
        for (int o = 0; o < 4; o++) {
            up2(vv[o][0], vv[o][1], acc[o][r][0]);
            up2(vv[o][2], vv[o][3], acc[o][r][1]);
            #pragma unroll
            for (int c = 0; c < 4; c++) vv[o][c] += bv[o];
        }
        int gy = y0 + pr4 + r + 1;
        #pragma unroll
        for (int c = 0; c < 4; c++) {
            u16 hv[4], lv[4];
            #pragma unroll
            for (int o = 0; o < 4; o++) {
                __nv_bfloat16 h = __float2bfloat16(vv[o][c]);
                hv[o] = __bfloat16_as_ushort(h);
                lv[o] = __bfloat16_as_ushort(__float2bfloat16(vv[o][c] - __bfloat162float(h)));
            }
            size_t off = ((size_t)(n * 34 + gy) * 34 + x0 + pc4 + c + 1) * 256 + oc0 + (ocg << 2);
            *(uint2*)&oh[off] = *(uint2*)hv;
            *(uint2*)&ol[off] = *(uint2*)lv;
        }
    }
}

// -------- Wo conv: 128->3, tanh (reads fp32 NCHW), IC_BLK=4, float4 LDG + scalar STS --------
__global__ __launch_bounds__(256) void convWo_kernel(
    const float* __restrict__ in, const float* __restrict__ w,
    const float* __restrict__ bias, float* __restrict__ out)
{
    __shared__ float s_w[3456];
    __shared__ __align__(16) float s_in[4][10][260];
    int n = blockIdx.x >> 5;
    int y0 = (blockIdx.x & 31) << 3;
    int tid = threadIdx.x;
    int rowg = tid >> 6;
    int c4 = (tid & 63) << 2;
    for (int e = tid; e < 3456; e += 256) s_w[e] = w[e];
    // x-edge columns are always OOB (gx = -1, 256): zero once.
    for (int e = tid; e < 4 * 10; e += 256) {
        int ic = e / 10, rr = e - ic * 10;
        s_in[ic][rr][0] = 0.0f;
        s_in[ic][rr][257] = 0.0f;
    }
    ull acc[3][2][2];
    #pragma unroll
    for (int ch = 0; ch < 3; ch++)
        #pragma unroll
        for (int r = 0; r < 2; r++) { acc[ch][r][0] = 0; acc[ch][r][1] = 0; }
    const float* in_n = in + (size_t)n * 128 * 65536;
    for (int ic0 = 0; ic0 < 128; ic0 += 4) {
        __syncthreads();
        for (int e = tid; e < 4 * 10 * 64; e += 256) {
            int ic = e / 640, rem = e - ic * 640;
            int rr = rem / 64, g = rem - rr * 64;
            int gy = y0 - 1 + rr;
            float4 v = make_float4(0.0f, 0.0f, 0.0f, 0.0f);
            if ((unsigned)gy < 256u)
                v = *(const float4*)&in_n[(size_t)(ic0 + ic) * 65536 + gy * 256 + (g << 2)];
            float* dp = &s_in[ic][rr][1 + (g << 2)];
            dp[0] = v.x; dp[1] = v.y; dp[2] = v.z; dp[3] = v.w;
        }
        __syncthreads();
        #pragma unroll
        for (int ic = 0; ic < 4; ic++)
            #pragma unroll
            for (int ky = 0; ky < 3; ky++) {
                ull P[2][5];
                #pragma unroll
                for (int r = 0; r < 2; r++) {
                    const float* rp = &s_in[ic][(rowg << 1) + r + ky][c4];
                    float4 v4 = *(const float4*)rp;
                    float2 v2 = *(const float2*)(rp + 4);
                    P[r][0] = pk2(v4.x, v4.y); P[r][1] = pk2(v4.y, v4.z);
                    P[r][2] = pk2(v4.z, v4.w); P[r][3] = pk2(v4.w, v2.x);
                    P[r][4] = pk2(v2.x, v2.y);
                }
                #pragma unroll
                for (int kx = 0; kx < 3; kx++)
                    #pragma unroll
                    for (int ch = 0; ch < 3; ch++) {
                        ull wb = bc2(s_w[ch * 1152 + (ic0 + ic) * 9 + ky * 3 + kx]);
                        #pragma unroll
                        for (int r = 0; r < 2; r++) {
                            fma2(acc[ch][r][0], wb, P[r][kx]);
                            fma2(acc[ch][r][1], wb, P[r][kx + 2]);
                        }
                    }
            }
    }
    #pragma unroll
    for (int ch = 0; ch < 3; ch++) {
        float bv = bias[ch];
        #pragma unroll
        for (int r = 0; r < 2; r++) {
            int y = y0 + (rowg << 1) + r;
            float f0, f1, f2, f3;
            up2(f0, f1, acc[ch][r][0]); up2(f2, f3, acc[ch][r][1]);
            *(float4*)&out[((size_t)(n * 3 + ch) << 16) + y * 256 + c4] =
                make_float4(tanhf(f0 + bv), tanhf(f1 + bv), tanhf(f2 + bv), tanhf(f3 + bv));
        }
    }
}

// -------- MMA weight prep --------
__global__ void wprep_kernel(const float* __restrict__ w, int OC, int IC, int trans)
{
    int KC = IC >> 5;
    int tot = KC * 9 * OC * 32;
    u16* dst = (u16*)g_wscr;
    for (int idx = blockIdx.x * blockDim.x + threadIdx.x; idx < tot; idx += gridDim.x * blockDim.x) {
        int j = idx & 31;
        int t = idx >> 5;
        int oc = t % OC; t /= OC;
        int tap = t % 9;
        int kc = t / 9;
        float v = trans ? w[((size_t)(kc * 32 + j) * OC + oc) * 9 + tap]
                        : w[((size_t)oc * IC + kc * 32 + j) * 9 + tap];
        __nv_bfloat16 h = __float2bfloat16(v);
        __nv_bfloat16 l = __float2bfloat16(v - __bfloat162float(h));
        size_t b = ((((size_t)kc * 9 + tap) * 2 + 0) * OC + oc) * 32 + j;
        size_t b2 = ((((size_t)kc * 9 + tap) * 2 + 1) * OC + oc) * 32 + j;
        dst[b] = __bfloat16_as_ushort(h);
        dst[b2] = __bfloat16_as_ushort(l);
    }
}

// -------- pad-ring zero --------
__global__ void ring_kernel(u16* __restrict__ oh, u16* __restrict__ ol, int C, int H, int W)
{
    int Hp = H + 2, Wp = W + 2, IC8 = C >> 3;
    int per = (2 * Wp + 2 * H) * IC8;
    int tot = 8 * per;
    uint4 z = make_uint4(0, 0, 0, 0);
    uint4* h4 = (uint4*)oh;
    uint4* l4 = (uint4*)ol;
    for (int idx = blockIdx.x * blockDim.x + threadIdx.x; idx < tot; idx += gridDim.x * blockDim.x) {
        int n = idx / per, r = idx % per;
        int pix = r / IC8, c = r % IC8;
        int y, x;
        if (pix < Wp) { y = 0; x = pix; }
        else if (pix < 2 * Wp) { y = Hp - 1; x = pix - Wp; }
        else { int q = pix - 2 * Wp; y = 1 + (q >> 1); x = (q & 1) ? Wp - 1 : 0; }
        size_t o = ((size_t)(n * Hp + y) * Wp + x) * IC8 + c;
        h4[o] = z; l4[o] = z;
    }
}

// -------- mma.sync conv 3x3 s1 p1 (3-pass hi/lo), cp.async, R rows/block --------
// B fragments loaded pairwise via ldmatrix.x4 (lanes 16-31 -> nt+1).
template<int NT, int R>
__global__ __launch_bounds__(256) void conv_mma_kernel(
    const u16* __restrict__ xh, const u16* __restrict__ xl,
    const float* __restrict__ bias,
    float* __restrict__ outf, u16* __restrict__ oh, u16* __restrict__ ol,
    int KC, int H, int W, int OC, int IC, int mode)
{
    extern __shared__ __align__(16) u16 sm[];
    const int PX = NT * 16;
    int segs = W / PX;
    int yb = blockIdx.x / segs, x0 = (blockIdx.x % segs) * PX;
    int y0 = yb * R;
    int oc0 = blockIdx.y << 7, n = blockIdx.z;
    int tid = threadIdx.x, wid = tid >> 5, l = tid & 31;
    int ocg = wid & 3, pxg = wid >> 2;
    int Hp = H + 2, Wp = W + 2;
    uint32_t sbase = smem_u32(sm);
    const u16* gw = (const u16*)g_wscr;
    float d[2][R][NT][4];
    #pragma unroll
    for (int mt = 0; mt < 2; mt++)
        #pragma unroll
        for (int r = 0; r < R; r++)
            #pragma unroll
            for (int nt = 0; nt < NT; nt++)
                #pragma unroll
                for (int i = 0; i < 4; i++) d[mt][r][nt][i] = 0.0f;

    const int pc = (PX + 2) * 4;
    for (int kc = 0; kc < KC; kc++)
        for (int ky = 0; ky < 3; ky++) {
            __syncthreads();
            for (int e = tid; e < 3072; e += 256) {
                int j8 = e & 3, oc = (e >> 2) & 127, blk = e >> 9;
                int kx = blk % 3, hl = blk / 3;
                const uint4* src = (const uint4*)(gw +
                    ((((size_t)kc * 9 + ky * 3 + kx) * 2 + hl) * OC + oc0 + oc) * 32) + j8;
                CPA16(sbase + (uint32_t)(blk * 128 + oc) * 80 + j8 * 16, src);
            }
            for (int e = tid; e < R * 2 * pc; e += 256) {
                int r = e / (2 * pc);
                int e2 = e - r * 2 * pc;
                int hl = e2 >= pc; int rr = e2 - hl * pc;
                int p = rr >> 2, j8 = rr & 3;
                const u16* gx = hl ? xl : xh;
                const uint4* src = (const uint4*)(gx +
                    ((size_t)(n * Hp + y0 + r + ky) * Wp + x0 + p) * IC + (kc << 5)) + j8;
                CPA16(sbase + 61440u + (uint32_t)((r * 2 + hl) * (PX + 2) + p) * 80 + j8 * 16, src);
            }
            CP_COMMIT();
            CP_WAIT0();
            __syncthreads();
            for (int kx = 0; kx < 3; kx++)
                #pragma unroll
                for (int ks = 0; ks < 2; ks++) {
                    uint32_t Ah[2][4], Al[2][4];
                    #pragma unroll
                    for (int mt = 0; mt < 2; mt++) {
                        int row = ocg * 32 + mt * 16 + (l & 15);
                        uint32_t a = sbase + (uint32_t)(kx * 128 + row) * 80 + ks * 32 + (l >> 4) * 16;
                        LDSM4(Ah[mt], a);
                        LDSM4(Al[mt], a + 3 * 128 * 80);
                    }
                    #pragma unroll
                    for (int r = 0; r < R; r++) {
                        uint32_t Bh[NT][2], Bl[NT][2];
                        #pragma unroll
                        for (int np = 0; np < NT / 2; np++) {
                            int p = pxg * (NT * 8) + np * 16 + ((l >> 4) << 3) + (l & 7) + kx;
                            uint32_t b = sbase + 61440 + (uint32_t)((r * 2) * (PX + 2) + p) * 80
                                       + ks * 32 + (((l >> 3) & 1) * 16);
                            LDSM4S(Bh[2 * np][0], Bh[2 * np][1],
                                   Bh[2 * np + 1][0], Bh[2 * np + 1][1], b);
                            LDSM4S(Bl[2 * np][0], Bl[2 * np][1],
                                   Bl[2 * np + 1][0], Bl[2 * np + 1][1], b + (PX + 2) * 80);
                        }
                        #pragma unroll
                        for (int mt = 0; mt < 2; mt++)
                            #pragma unroll
                            for (int nt = 0; nt < NT; nt++) {
                                MMA(d[mt][r][nt], Ah[mt], Bh[nt]);
                                MMA(d[mt][r][nt], Ah[mt], Bl[nt]);
                                MMA(d[mt][r][nt], Al[mt], Bh[nt]);
                            }
                    }
                }
        }
    if (mode) {
        size_t plane = (size_t)H * W;
        #pragma unroll
        for (int mt = 0; mt < 2; mt++) {
            int ocr = oc0 + ocg * 32 + mt * 16 + (l >> 2);
            float b0 = bias[ocr], b8 = bias[ocr + 8];
            #pragma unroll
            for (int r = 0; r < R; r++) {
                float* ob = outf + ((size_t)n * OC + ocr) * plane + (size_t)(y0 + r) * W;
                #pragma unroll
                for (int nt = 0; nt < NT; nt++) {
                    int px = x0 + pxg * (NT * 8) + nt * 8 + (l & 3) * 2;
                    *(float2*)(ob + px) = make_float2(
                        fmaxf(d[mt][r][nt][0] + b0, 0.0f), fmaxf(d[mt][r][nt][1] + b0, 0.0f));
                    *(float2*)(ob + 8 * plane + px) = make_float2(
                        fmaxf(d[mt][r][nt][2] + b8, 0.0f), fmaxf(d[mt][r][nt][3] + b8, 0.0f));
                }
            }
        }
    } else {
        #pragma unroll
        for (int mt = 0; mt < 2; mt++) {
            int ocr = oc0 + ocg * 32 + mt * 16 + (l >> 2);
            float b0 = bias[ocr], b8 = bias[ocr + 8];
            #pragma unroll
            for (int r = 0; r < R; r++)
                #pragma unroll
                for (int nt = 0; nt < NT; nt++) {
                    int px = x0 + pxg * (NT * 8) + nt * 8 + (l & 3) * 2;
                    size_t base2 = ((size_t)(n * Hp + y0 + r + 1) * Wp + px + 1) * OC;
                    stsplit(oh, ol, base2 + ocr,          fmaxf(d[mt][r][nt][0] + b0, 0.0f));
                    stsplit(oh, ol, base2 + OC + ocr,     fmaxf(d[mt][r][nt][1] + b0, 0.0f));
                    stsplit(oh, ol, base2 + ocr + 8,      fmaxf(d[mt][r][nt][2] + b8, 0.0f));
                    stsplit(oh, ol, base2 + OC + ocr + 8, fmaxf(d[mt][r][nt][3] + b8, 0.0f));
                }
        }
    }
}

// -------- mma.sync DECONV k3 s2 p1 op1 + relu, cp.async --------
// ky=1 and ky=2 read the same input row; pixel staging skipped at ky==2.
// B fragments loaded pairwise via ldmatrix.x4.
template<int NT>
__global__ __launch_bounds__(256) void deconv_mma_kernel(
    const u16* __restrict__ xh, const u16* __restrict__ xl,
    u16* __restrict__ oh, u16* __restrict__ ol,
    const float* __restrict__ bias,
    int KC, int H, int W, int OC, int IC)
{
    extern __shared__ __align__(16) u16 sm[];
    const int PX = NT * 16;
    int segs = W / PX;
    int y = blockIdx.x / segs, x0 = (blockIdx.x % segs) * PX;
    int oc0 = blockIdx.y << 7, n = blockIdx.z;
    int tid = threadIdx.x, wid = tid >> 5, l = tid & 31;
    int ocg = wid & 3, pxg = wid >> 2;
    int Hp = H + 2, Wp = W + 2;
    uint32_t sbase = smem_u32(sm);
    const u16* gw = (const u16*)g_wscr;
    float d[2][2][2][NT][4];                 // [mt][dy][dx][nt][4]
    #pragma unroll
    for (int mt = 0; mt < 2; mt++)
        #pragma unroll
        for (int a = 0; a < 2; a++)
            #pragma unroll
            for (int b = 0; b < 2; b++)
                #pragma unroll
                for (int nt = 0; nt < NT; nt++)
                    #pragma unroll
                    for (int i = 0; i < 4; i++) d[mt][a][b][nt][i] = 0.0f;

    const int pcd = (PX + 1) * 4;
    for (int kc = 0; kc < KC; kc++)
        for (int ky = 0; ky < 3; ky++) {
            __syncthreads();
            for (int e = tid; e < 3072; e += 256) {
                int j8 = e & 3, oc = (e >> 2) & 127, blk = e >> 9;
                int kx = blk % 3, hl = blk / 3;
                const uint4* src = (const uint4*)(gw +
                    ((((size_t)kc * 9 + ky * 3 + kx) * 2 + hl) * OC + oc0 + oc) * 32) + j8;
                CPA16(sbase + (uint32_t)(blk * 128 + oc) * 80 + j8 * 16, src);
            }
            if (ky != 2) {                   // ky==2 reuses ky==1's pixel row (y+1)
                int ry = y + 1 + (ky == 0);  // padded input row
                for (int e = tid; e < 2 * pcd; e += 256) {
                    int hl = e >= pcd; int r = e - hl * pcd;
                    int p = r >> 2, j8 = r & 3;
                    const u16* gx = hl ? xl : xh;
                    const uint4* src = (const uint4*)(gx +
                        ((size_t)(n * Hp + ry) * Wp + x0 + 1 + p) * IC + (kc << 5)) + j8;
                    CPA16(sbase + 61440u + (uint32_t)(hl * (PX + 1) + p) * 80 + j8 * 16, src);
                }
            }
            CP_COMMIT();
            CP_WAIT0();
            __syncthreads();
            int dy = (ky != 1);
            #pragma unroll
            for (int ks = 0; ks < 2; ks++) {
                uint32_t Bf[2][2][NT][2];    // [hl][shift][nt][2]
                #pragma unroll
                for (int sh = 0; sh < 2; sh++)
                    #pragma unroll
                    for (int np = 0; np < NT / 2; np++) {
                        int p = pxg * (NT * 8) + np * 16 + ((l >> 4) << 3) + (l & 7) + sh;
                        uint32_t b = sbase + 61440 + (uint32_t)p * 80 + ks * 32 + (((l >> 3) & 1) * 16);
                        LDSM4S(Bf[0][sh][2 * np][0], Bf[0][sh][2 * np][1],
                               Bf[0][sh][2 * np + 1][0], Bf[0][sh][2 * np + 1][1], b);
                        LDSM4S(Bf[1][sh][2 * np][0], Bf[1][sh][2 * np][1],
                               Bf[1][sh][2 * np + 1][0], Bf[1][sh][2 * np + 1][1],
                               b + (PX + 1) * 80);
                    }
                for (int kx = 0; kx < 3; kx++) {
                    int sh = (kx == 0), dxp = (kx != 1);
                    uint32_t Ah[2][4], Al[2][4];
                    #pragma unroll
                    for (int mt = 0; mt < 2; mt++) {
                        int row = ocg * 32 + mt * 16 + (l & 15);
                        uint32_t a = sbase + (uint32_t)(kx * 128 + row) * 80 + ks * 32 + (l >> 4) * 16;
                        LDSM4(Ah[mt], a);
                        LDSM4(Al[mt], a + 3 * 128 * 80);
                    }
                    #pragma unroll
                    for (int mt = 0; mt < 2; mt++)
                        #pragma unroll
                        for (int nt = 0; nt < NT; nt++) {
                            MMA(d[mt][dy][dxp][nt], Ah[mt], Bf[0][sh][nt]);
                            MMA(d[mt][dy][dxp][nt], Ah[mt], Bf[1][sh][nt]);
                            MMA(d[mt][dy][dxp][nt], Al[mt], Bf[0][sh][nt]);
                        }
                }
            }
        }
    int OHp = 2 * H + 2, OWp = 2 * W + 2;
    #pragma unroll
    for (int mt = 0; mt < 2; mt++) {
        int ocr = oc0 + ocg * 32 + mt * 16 + (l >> 2);
        float b0 = bias[ocr], b8 = bias[ocr + 8];
        #pragma unroll
        for (int dy2 = 0; dy2 < 2; dy2++)
            #pragma unroll
            for (int dxp = 0; dxp < 2; dxp++)
                #pragma unroll
                for (int nt = 0; nt < NT; nt++) {
                    int p0 = x0 + pxg * (NT * 8) + nt * 8 + 2 * (l & 3);
                    size_t base2 = ((size_t)(n * OHp + 2 * y + dy2 + 1) * OWp + 2 * p0 + dxp + 1) * OC;
                    stsplit(oh, ol, base2 + ocr,              fmaxf(d[mt][dy2][dxp][nt][0] + b0, 0.0f));
                    stsplit(oh, ol, base2 + 2 * OC + ocr,     fmaxf(d[mt][dy2][dxp][nt][1] + b0, 0.0f));
                    stsplit(oh, ol, base2 + ocr + 8,          fmaxf(d[mt][dy2][dxp][nt][2] + b8, 0.0f));
                    stsplit(oh, ol, base2 + 2 * OC + ocr + 8, fmaxf(d[mt][dy2][dxp][nt][3] + b8, 0.0f));
                }
    }
}

// -------- host --------
static void conv_mma(const float* w, const float* b, const u16* xh, const u16* xl,
                     u16* oh, u16* ol, float* outf, int IC, int OC, int H, int W, int mode)
{
    wprep_kernel<<<128, 256>>>(w, OC, IC, 0);
    if (mode == 0) ring_kernel<<<256, 256>>>(oh, ol, OC, H, W);
    if (W >= 128) {
        dim3 grid((W / 128) * (H / 2), OC / 128, 8);
        conv_mma_kernel<8, 2><<<grid, 256, 61440 + 2 * 2 * 130 * 80>>>(
            xh, xl, b, outf, oh, ol, IC / 32, H, W, OC, IC, mode);
    } else {
        dim3 grid((W / 64) * (H / 4), OC / 128, 8);
        conv_mma_kernel<4, 4><<<grid, 256, 61440 + 4 * 2 * 66 * 80>>>(
            xh, xl, b, outf, oh, ol, IC / 32, H, W, OC, IC, mode);
    }
}

static void deconv_mma(const float* w, const float* b, const u16* xh, const u16* xl,
                       u16* oh, u16* ol, int IC, int OC, int H, int W)
{
    wprep_kernel<<<128, 256>>>(w, OC, IC, 1);
    ring_kernel<<<256, 256>>>(oh, ol, OC, 2 * H, 2 * W);
    if (W >= 64) {
        dim3 grid((W / 64) * H, OC / 128, 8);
        deconv_mma_kernel<4><<<grid, 256, 61440 + 2 * 65 * 80>>>(
            xh, xl, oh, ol, b, IC / 32, H, W, OC, IC);
    } else {
        dim3 grid((W / 32) * H, OC / 128, 8);
        deconv_mma_kernel<2><<<grid, 256, 61440 + 2 * 33 * 80>>>(
            xh, xl, oh, ol, b, IC / 32, H, W, OC, IC);
    }
}

extern "C" void kernel_launch(void* const* d_in, const int* in_sizes, int n_in,
                              void* d_out, int out_size)
{
    const float* x   = (const float*)d_in[0];
    const float* We0 = (const float*)d_in[1];
    const float* be0 = (const float*)d_in[2];
    const float* We1 = (const float*)d_in[3];
    const float* be1 = (const float*)d_in[4];
    const float* Wi  = (const float*)d_in[5];
    const float* bi  = (const float*)d_in[6];
    const float* Wd1 = (const float*)d_in[7];
    const float* bd1 = (const float*)d_in[8];
    const float* Wc1 = (const float*)d_in[9];
    const float* bc1 = (const float*)d_in[10];
    const float* Wd2 = (const float*)d_in[11];
    const float* bd2 = (const float*)d_in[12];
    const float* Wc2 = (const float*)d_in[13];
    const float* bc2_ = (const float*)d_in[14];
    const float* Wd3 = (const float*)d_in[15];
    const float* bd3 = (const float*)d_in[16];
    const float* Wc3 = (const float*)d_in[17];
    const float* bc3 = (const float*)d_in[18];
    const float* Wo  = (const float*)d_in[19];
    const float* bo  = (const float*)d_in[20];
    float* out = (float*)d_out;

    static int once = 0;
    if (!once) {
        cudaFuncSetAttribute(conv_mma_kernel<8, 2>, cudaFuncAttributeMaxDynamicSharedMemorySize, 104000);
        cudaFuncSetAttribute(conv_mma_kernel<4, 4>, cudaFuncAttributeMaxDynamicSharedMemorySize, 104000);
        cudaFuncSetAttribute(deconv_mma_kernel<4>, cudaFuncAttributeMaxDynamicSharedMemorySize, 104000);
        cudaFuncSetAttribute(deconv_mma_kernel<2>, cudaFuncAttributeMaxDynamicSharedMemorySize, 104000);
        once = 1;
    }

    float *h3buf, *routed;
    u16 *pAh, *pAl, *pBh, *pBl;
    cudaGetSymbolAddress((void**)&h3buf, g_bufA);
    cudaGetSymbolAddress((void**)&routed, g_routed);
    cudaGetSymbolAddress((void**)&pAh, g_pAh);
    cudaGetSymbolAddress((void**)&pAl, g_pAl);
    cudaGetSymbolAddress((void**)&pBh, g_pBh);
    cudaGetSymbolAddress((void**)&pBl, g_pBl);

    encoder_kernel<<<160, 256>>>(x, We0, be0, We1, be1);
    entropy_kernel<<<2048, 256>>>(x);
    median_kernel<<<1, 1024>>>();
    int write_aux = (out_size >= OUT_FULL) ? 1 : 0;
    route_kernel<<<128, 256>>>(out, write_aux);

    ring_kernel<<<256, 256>>>(pAh, pAl, 256, 32, 32);
    dim3 gWi(4, 4, 8);
    convWi_kernel<<<gWi, 256>>>(routed, Wi, bi, pAh, pAl);
    deconv_mma(Wd1, bd1, pAh, pAl, pBh, pBl, 256, 256, 32, 32);
    conv_mma(Wc1, bc1, pBh, pBl, pAh, pAl, nullptr, 256, 256, 64, 64, 0);
    deconv_mma(Wd2, bd2, pAh, pAl, pBh, pBl, 256, 128, 64, 64);
    conv_mma(Wc2, bc2_, pBh, pBl, pAh, pAl, nullptr, 128, 128, 128, 128, 0);
    deconv_mma(Wd3, bd3, pAh, pAl, pBh, pBl, 128, 128, 128, 128);
    conv_mma(Wc3, bc3, pBh, pBl, nullptr, nullptr, h3buf, 128, 128, 256, 256, 1);
    convWo_kernel<<<256, 256>>>(h3buf, Wo, bo, out);
}